// round 1
// baseline (speedup 1.0000x reference)
#include <cuda_runtime.h>
#include <cstdint>

// ---------------------------------------------------------------------------
// LinearSelfAttentionBlock  (B=4, C=512, L=4096, H=8, DH=64, MLP=2048)
// Round 1: full fp32, custom SIMT SGEMM + fused epilogues.
// Zero-token of K/V handled analytically (never materialized).
// ---------------------------------------------------------------------------

constexpr int NB   = 4;
constexpr int NC   = 512;
constexpr int NL   = 4096;
constexpr int NH   = 8;
constexpr int NDH  = 64;
constexpr int NMLP = 2048;
constexpr int NM   = NB * NL;          // 16384 rows

// ------------------------- scratch (device globals) ------------------------
__device__ float g_xf   [NM * NC];
__device__ float g_Q    [NM * NC];
__device__ float g_K    [NM * NC];
__device__ float g_V    [NM * NC];
__device__ float g_phiQ [NM * NC];
__device__ float g_phiK [NM * NC];
__device__ float g_attn [NM * NC];
__device__ float g_aln  [NM * NC];
__device__ float g_res  [NM * NC];
__device__ float g_hid  [NM * NMLP];
__device__ float g_probe[NB * NC];
__device__ float g_score[NB * NH * NL];
__device__ float g_bot  [NB * NH * NL];
__device__ float g_s0   [NB * NH];
__device__ float g_kv   [NB * NH * NDH * NDH];
__device__ float g_ksum [NB * NH * NDH];

// ------------------------- transpose x[B,C,L] -> xf[B,L,C] -----------------
__global__ void transpose_in_kernel(const float* __restrict__ x, float* __restrict__ xf)
{
    __shared__ float tile[32][33];
    int b  = blockIdx.z;
    int l0 = blockIdx.x * 32, c0 = blockIdx.y * 32;
    const float* xb = x + (size_t)b * NC * NL;
    #pragma unroll
    for (int i = threadIdx.y; i < 32; i += 8)
        tile[i][threadIdx.x] = xb[(size_t)(c0 + i) * NL + l0 + threadIdx.x];
    __syncthreads();
    float* xfb = xf + (size_t)b * NL * NC;
    #pragma unroll
    for (int i = threadIdx.y; i < 32; i += 8)
        xfb[(size_t)(l0 + i) * NC + c0 + threadIdx.x] = tile[threadIdx.x][i];
}

// --------------- final: out[b,c,l] = res[b,l,c] + x[b,c,l] -----------------
__global__ void final_kernel(const float* __restrict__ res, const float* __restrict__ x,
                             float* __restrict__ out)
{
    __shared__ float tile[32][33];
    int b  = blockIdx.z;
    int l0 = blockIdx.x * 32, c0 = blockIdx.y * 32;
    const float* rb = res + (size_t)b * NL * NC;
    #pragma unroll
    for (int i = threadIdx.y; i < 32; i += 8)
        tile[i][threadIdx.x] = rb[(size_t)(l0 + i) * NC + c0 + threadIdx.x];
    __syncthreads();
    const float* xb = x + (size_t)b * NC * NL;
    float*       ob = out + (size_t)b * NC * NL;
    #pragma unroll
    for (int i = threadIdx.y; i < 32; i += 8) {
        size_t idx = (size_t)(c0 + i) * NL + l0 + threadIdx.x;
        ob[idx] = tile[threadIdx.x][i] + xb[idx];
    }
}

// ------------------------- SGEMM 128x128x8 + fused epilogue ----------------
// EPI: 0 = +bias ; 1 = tanh(+bias)+1 ; 2 = gelu_exact(+bias) ; 3 = +bias+resid
#define BM 128
#define BN 128
#define BKK 8
template <int EPI>
__global__ void gemm_kernel(const float* __restrict__ A, const float* __restrict__ W,
                            const float* __restrict__ bias, float* __restrict__ Out,
                            int M, int N, int K, const float* __restrict__ resid)
{
    __shared__ float As[BKK][BM];
    __shared__ float Bs[BKK][BN];
    int tid = threadIdx.x;
    int br0 = blockIdx.y * BM;
    int bc0 = blockIdx.x * BN;

    int tr = (tid >> 4) * 8;      // 0..120
    int tc = (tid & 15) * 8;      // 0..120

    int aRow = tid >> 1;          // 0..127
    int aCol = (tid & 1) * 4;     // 0 or 4
    int bRow = tid >> 5;          // 0..7
    int bCol = (tid & 31) * 4;    // 0..124

    float acc[8][8];
    #pragma unroll
    for (int i = 0; i < 8; i++)
        #pragma unroll
        for (int j = 0; j < 8; j++) acc[i][j] = 0.f;

    for (int k0 = 0; k0 < K; k0 += BKK) {
        float4 av = *reinterpret_cast<const float4*>(
            &A[(size_t)(br0 + aRow) * K + k0 + aCol]);
        As[aCol + 0][aRow] = av.x;
        As[aCol + 1][aRow] = av.y;
        As[aCol + 2][aRow] = av.z;
        As[aCol + 3][aRow] = av.w;
        *reinterpret_cast<float4*>(&Bs[bRow][bCol]) =
            *reinterpret_cast<const float4*>(&W[(size_t)(k0 + bRow) * N + bc0 + bCol]);
        __syncthreads();
        #pragma unroll
        for (int k = 0; k < BKK; k++) {
            float4 a0 = *reinterpret_cast<const float4*>(&As[k][tr]);
            float4 a1 = *reinterpret_cast<const float4*>(&As[k][tr + 4]);
            float4 b0 = *reinterpret_cast<const float4*>(&Bs[k][tc]);
            float4 b1 = *reinterpret_cast<const float4*>(&Bs[k][tc + 4]);
            float ar[8] = {a0.x, a0.y, a0.z, a0.w, a1.x, a1.y, a1.z, a1.w};
            float brv[8] = {b0.x, b0.y, b0.z, b0.w, b1.x, b1.y, b1.z, b1.w};
            #pragma unroll
            for (int i = 0; i < 8; i++)
                #pragma unroll
                for (int j = 0; j < 8; j++) acc[i][j] += ar[i] * brv[j];
        }
        __syncthreads();
    }

    #pragma unroll
    for (int i = 0; i < 8; i++) {
        size_t rowoff = (size_t)(br0 + tr + i) * N;
        #pragma unroll
        for (int j = 0; j < 8; j++) {
            int col = bc0 + tc + j;
            float v = acc[i][j] + bias[col];
            if (EPI == 1) v = tanhf(v) + 1.0f;
            else if (EPI == 2) v = 0.5f * v * (1.0f + erff(v * 0.7071067811865475f));
            else if (EPI == 3) v += resid[rowoff + col];
            Out[rowoff + col] = v;
        }
    }
}

// ------------------------- layernorm over rows of 512 ----------------------
__global__ void layernorm_kernel(const float* __restrict__ in, float* __restrict__ out,
                                 const float* __restrict__ gamma, const float* __restrict__ beta)
{
    int row = blockIdx.x;
    int tid = threadIdx.x;                      // 128 threads, 4 floats each
    const float4 v = reinterpret_cast<const float4*>(in + (size_t)row * NC)[tid];
    __shared__ float sh[4];

    float s = v.x + v.y + v.z + v.w;
    #pragma unroll
    for (int o = 16; o > 0; o >>= 1) s += __shfl_xor_sync(0xffffffffu, s, o);
    if ((tid & 31) == 0) sh[tid >> 5] = s;
    __syncthreads();
    float mean = (sh[0] + sh[1] + sh[2] + sh[3]) * (1.0f / NC);
    __syncthreads();

    float dx = v.x - mean, dy = v.y - mean, dz = v.z - mean, dw = v.w - mean;
    float q = dx * dx + dy * dy + dz * dz + dw * dw;
    #pragma unroll
    for (int o = 16; o > 0; o >>= 1) q += __shfl_xor_sync(0xffffffffu, q, o);
    if ((tid & 31) == 0) sh[tid >> 5] = q;
    __syncthreads();
    float var = (sh[0] + sh[1] + sh[2] + sh[3]) * (1.0f / NC);
    float inv = rsqrtf(var + 1e-5f);

    float4 g  = reinterpret_cast<const float4*>(gamma)[tid];
    float4 bb = reinterpret_cast<const float4*>(beta)[tid];
    float4 o4;
    o4.x = dx * inv * g.x + bb.x;
    o4.y = dy * inv * g.y + bb.y;
    o4.z = dz * inv * g.z + bb.z;
    o4.w = dw * inv * g.w + bb.w;
    reinterpret_cast<float4*>(out + (size_t)row * NC)[tid] = o4;
}

// ------------------------- misc small kernels ------------------------------
__global__ void zero_kernel(float* __restrict__ p, int n)
{
    int i = blockIdx.x * blockDim.x + threadIdx.x;
    if (i < n) p[i] = 0.f;
}

// probe[b,c] += sum over 128 rows of Q[b, l, c]
__global__ void probe_kernel(const float* __restrict__ Q, float* __restrict__ probe)
{
    int b = blockIdx.x, chunk = blockIdx.y;
    int c = threadIdx.x;                        // 512 threads
    float s = 0.f;
    size_t base = ((size_t)b * NL + (size_t)chunk * 128) * NC + c;
    for (int i = 0; i < 128; i++) s += Q[base + (size_t)i * NC];
    atomicAdd(&probe[b * NC + c], s);
}

// out[b,h,l] = scale * dot(rows[b,l, h*64 : h*64+64], vecs[b, h*64 : ...])
__global__ void headdot_kernel(const float* __restrict__ rows, const float* __restrict__ vecs,
                               float* __restrict__ out, float scale)
{
    int warp = (blockIdx.x * blockDim.x + threadIdx.x) >> 5;
    int lane = threadIdx.x & 31;
    if (warp >= NB * NL) return;
    int b = warp / NL, l = warp % NL;
    const float* row = rows + (size_t)warp * NC;
    const float* vec = vecs + (size_t)b * NC;
    float p[8];
    #pragma unroll
    for (int h = 0; h < 8; h++) p[h] = 0.f;
    #pragma unroll
    for (int j = 0; j < 16; j++) {
        int c = lane + 32 * j;
        p[j >> 1] += row[c] * vec[c];
    }
    #pragma unroll
    for (int h = 0; h < 8; h++) {
        float v = p[h];
        #pragma unroll
        for (int o = 16; o > 0; o >>= 1) v += __shfl_xor_sync(0xffffffffu, v, o);
        p[h] = v;
    }
    if (lane == 0) {
        #pragma unroll
        for (int h = 0; h < 8; h++)
            out[((size_t)b * NH + h) * NL + l] = p[h] * scale;
    }
}

// softmax over [score(l=1..L), 0] per (b,h); writes normalized probs + s0
__global__ void softmax_kernel(float* __restrict__ score, float* __restrict__ s0)
{
    int bh = blockIdx.x;
    float* s = score + (size_t)bh * NL;
    int tid = threadIdx.x;                      // 256 threads
    __shared__ float sh[8];
    __shared__ float bc2[2];

    float m = 0.0f;                             // includes zero-token score 0
    for (int i = tid; i < NL; i += 256) m = fmaxf(m, s[i]);
    #pragma unroll
    for (int o = 16; o > 0; o >>= 1) m = fmaxf(m, __shfl_xor_sync(0xffffffffu, m, o));
    if ((tid & 31) == 0) sh[tid >> 5] = m;
    __syncthreads();
    if (tid == 0) {
        float mm = sh[0];
        for (int i = 1; i < 8; i++) mm = fmaxf(mm, sh[i]);
        bc2[0] = mm;
    }
    __syncthreads();
    m = bc2[0];

    float sum = 0.f;
    for (int i = tid; i < NL; i += 256) sum += expf(s[i] - m);
    #pragma unroll
    for (int o = 16; o > 0; o >>= 1) sum += __shfl_xor_sync(0xffffffffu, sum, o);
    if ((tid & 31) == 0) sh[tid >> 5] = sum;
    __syncthreads();
    if (tid == 0) {
        float t = expf(-m);                     // zero token
        for (int i = 0; i < 8; i++) t += sh[i];
        bc2[1] = 1.0f / t;
    }
    __syncthreads();
    float inv = bc2[1];
    for (int i = tid; i < NL; i += 256) s[i] = expf(s[i] - m) * inv;
    if (tid == 0) s0[bh] = expf(-m) * inv;
}

// kv[b,h,d,e] += sum_l sc*phiK[..d]*V[..e] ; ksum[b,h,d] += sum_l sc*phiK[..d]
__global__ void kv_kernel(const float* __restrict__ phiK, const float* __restrict__ V,
                          const float* __restrict__ score, float* __restrict__ kv,
                          float* __restrict__ ksum)
{
    int bh = blockIdx.x, b = bh >> 3, h = bh & 7;
    int l0 = blockIdx.y * (NL / 8);             // 512-row chunk
    __shared__ float pks[8][64];
    __shared__ float vs[8][64];
    int tid = threadIdx.x;
    int d0 = (tid >> 4) << 2;
    int e0 = (tid & 15) << 2;
    float acc[4][4];
    #pragma unroll
    for (int i = 0; i < 4; i++)
        #pragma unroll
        for (int j = 0; j < 4; j++) acc[i][j] = 0.f;
    float ks[4] = {0.f, 0.f, 0.f, 0.f};

    const size_t base = ((size_t)b * NL) * NC + (size_t)h * 64;
    const float* scb = score + (size_t)bh * NL;

    for (int lt = 0; lt < NL / 8; lt += 8) {
        #pragma unroll
        for (int s = 0; s < 2; s++) {
            int idx = tid + (s << 8);
            int r = idx >> 6, col = idx & 63;
            int l = l0 + lt + r;
            size_t off = base + (size_t)l * NC + col;
            pks[r][col] = phiK[off] * scb[l];
            vs[r][col]  = V[off];
        }
        __syncthreads();
        #pragma unroll
        for (int r = 0; r < 8; r++) {
            float4 pk = *reinterpret_cast<const float4*>(&pks[r][d0]);
            float4 vv = *reinterpret_cast<const float4*>(&vs[r][e0]);
            float pa[4] = {pk.x, pk.y, pk.z, pk.w};
            float va[4] = {vv.x, vv.y, vv.z, vv.w};
            #pragma unroll
            for (int i = 0; i < 4; i++)
                #pragma unroll
                for (int j = 0; j < 4; j++) acc[i][j] += pa[i] * va[j];
            if (e0 == 0) {
                #pragma unroll
                for (int i = 0; i < 4; i++) ks[i] += pa[i];
            }
        }
        __syncthreads();
    }
    float* kvb = kv + (size_t)bh * 4096;
    #pragma unroll
    for (int i = 0; i < 4; i++)
        #pragma unroll
        for (int j = 0; j < 4; j++)
            atomicAdd(&kvb[(d0 + i) * 64 + e0 + j], acc[i][j]);
    if (e0 == 0) {
        #pragma unroll
        for (int i = 0; i < 4; i++) atomicAdd(&ksum[bh * 64 + d0 + i], ks[i]);
    }
}

// zero-token contribution: ksum += s0 * (tanh(bkk)+1)
__global__ void ksum_s0_kernel(const float* __restrict__ bkk, const float* __restrict__ s0,
                               float* __restrict__ ksum)
{
    int bh = blockIdx.x, h = bh & 7;
    int d = threadIdx.x;
    ksum[bh * 64 + d] += s0[bh] * (tanhf(bkk[h * 64 + d]) + 1.0f);
}

// out[b,l,h*64+e] = (sum_d phiQ[b,l,h*64+d]*kv[b,h,d,e]) / (bottom + 1e-6)
__global__ void attnout_kernel(const float* __restrict__ phiQ, const float* __restrict__ kv,
                               const float* __restrict__ bottom, float* __restrict__ out)
{
    int bh = blockIdx.y, b = bh >> 3, h = bh & 7;
    int ltile = blockIdx.x;
    __shared__ float kvs[4096];
    __shared__ float pqs[4][64];
    int tid = threadIdx.x;
    const float* kvb = kv + (size_t)bh * 4096;
    for (int i = tid; i < 4096; i += 256) kvs[i] = kvb[i];
    int rr = tid >> 6, e = tid & 63;
    size_t rowc = (size_t)b * NL + (size_t)ltile * 64;
    for (int r0 = 0; r0 < 64; r0 += 4) {
        __syncthreads();
        pqs[rr][e] = phiQ[(rowc + r0 + rr) * NC + h * 64 + e];
        __syncthreads();
        float num = 0.f;
        #pragma unroll
        for (int d = 0; d < 64; d++) num += pqs[rr][d] * kvs[d * 64 + e];
        int l = ltile * 64 + r0 + rr;
        float bot = bottom[(size_t)bh * NL + l] + 1e-6f;
        out[(rowc + r0 + rr) * NC + h * 64 + e] = num / bot;
    }
}

// ---------------------------------------------------------------------------
extern "C" void kernel_launch(void* const* d_in, const int* in_sizes, int n_in,
                              void* d_out, int out_size)
{
    (void)in_sizes; (void)n_in; (void)out_size;
    const float* x      = (const float*)d_in[0];
    const float* Wq     = (const float*)d_in[1];
    const float* bq     = (const float*)d_in[2];
    const float* gq     = (const float*)d_in[3];
    const float* betaq  = (const float*)d_in[4];
    const float* Wk     = (const float*)d_in[5];
    const float* bk     = (const float*)d_in[6];
    const float* gk     = (const float*)d_in[7];
    const float* betak  = (const float*)d_in[8];
    const float* Wv     = (const float*)d_in[9];
    const float* bv     = (const float*)d_in[10];
    const float* gv     = (const float*)d_in[11];
    const float* betav  = (const float*)d_in[12];
    const float* Wkq    = (const float*)d_in[13];
    const float* bkq    = (const float*)d_in[14];
    const float* Wkk    = (const float*)d_in[15];
    const float* bkk    = (const float*)d_in[16];
    const float* gat    = (const float*)d_in[17];
    const float* bat    = (const float*)d_in[18];
    const float* W1     = (const float*)d_in[19];
    const float* b1     = (const float*)d_in[20];
    const float* W2     = (const float*)d_in[21];
    const float* b2     = (const float*)d_in[22];
    float* out = (float*)d_out;

    float *xf, *Q, *K, *V, *phiQ, *phiK, *attn, *aln, *res, *hid;
    float *probe, *score, *bot, *s0, *kv, *ksum;
    cudaGetSymbolAddress((void**)&xf,    g_xf);
    cudaGetSymbolAddress((void**)&Q,     g_Q);
    cudaGetSymbolAddress((void**)&K,     g_K);
    cudaGetSymbolAddress((void**)&V,     g_V);
    cudaGetSymbolAddress((void**)&phiQ,  g_phiQ);
    cudaGetSymbolAddress((void**)&phiK,  g_phiK);
    cudaGetSymbolAddress((void**)&attn,  g_attn);
    cudaGetSymbolAddress((void**)&aln,   g_aln);
    cudaGetSymbolAddress((void**)&res,   g_res);
    cudaGetSymbolAddress((void**)&hid,   g_hid);
    cudaGetSymbolAddress((void**)&probe, g_probe);
    cudaGetSymbolAddress((void**)&score, g_score);
    cudaGetSymbolAddress((void**)&bot,   g_bot);
    cudaGetSymbolAddress((void**)&s0,    g_s0);
    cudaGetSymbolAddress((void**)&kv,    g_kv);
    cudaGetSymbolAddress((void**)&ksum,  g_ksum);

    dim3 tgrid(NL / 32, NC / 32, NB), tblk(32, 8);
    transpose_in_kernel<<<tgrid, tblk>>>(x, xf);

    dim3 gC(NC / BN, NM / BM);                  // (4, 128)
    gemm_kernel<0><<<gC, 256>>>(xf, Wq, bq, Q, NM, NC, NC, nullptr);
    gemm_kernel<0><<<gC, 256>>>(xf, Wk, bk, K, NM, NC, NC, nullptr);
    gemm_kernel<0><<<gC, 256>>>(xf, Wv, bv, V, NM, NC, NC, nullptr);

    layernorm_kernel<<<NM, 128>>>(Q, Q, gq, betaq);
    layernorm_kernel<<<NM, 128>>>(K, K, gk, betak);
    layernorm_kernel<<<NM, 128>>>(V, V, gv, betav);

    zero_kernel<<<(NB * NC + 255) / 256, 256>>>(probe, NB * NC);
    zero_kernel<<<(NB * NH * NDH * NDH + 255) / 256, 256>>>(kv, NB * NH * NDH * NDH);
    zero_kernel<<<(NB * NH * NDH + 255) / 256, 256>>>(ksum, NB * NH * NDH);

    probe_kernel<<<dim3(NB, 32), 512>>>(Q, probe);

    gemm_kernel<1><<<gC, 256>>>(Q, Wkq, bkq, phiQ, NM, NC, NC, nullptr);
    gemm_kernel<1><<<gC, 256>>>(K, Wkk, bkk, phiK, NM, NC, NC, nullptr);

    // score = (probe_sum/L) . K / sqrt(DH)
    headdot_kernel<<<(NB * NL) / 8, 256>>>(K, probe, score, 1.0f / ((float)NL * 8.0f));
    softmax_kernel<<<NB * NH, 256>>>(score, s0);

    kv_kernel<<<dim3(NB * NH, 8), 256>>>(phiK, V, score, kv, ksum);
    ksum_s0_kernel<<<NB * NH, 64>>>(bkk, s0, ksum);

    headdot_kernel<<<(NB * NL) / 8, 256>>>(phiQ, ksum, bot, 1.0f);
    attnout_kernel<<<dim3(NL / 64, NB * NH), 256>>>(phiQ, kv, bot, attn);

    layernorm_kernel<<<NM, 128>>>(attn, aln, gat, bat);

    dim3 gMLP(NMLP / BN, NM / BM);              // (16, 128)
    gemm_kernel<2><<<gMLP, 256>>>(aln, W1, b1, hid, NM, NMLP, NC, nullptr);
    gemm_kernel<3><<<gC, 256>>>(hid, W2, b2, res, NM, NC, NMLP, aln);

    final_kernel<<<tgrid, tblk>>>(res, x, out);
}

// round 3
// speedup vs baseline: 2.4540x; 2.4540x over previous
#include <cuda_runtime.h>
#include <cstdint>

// ---------------------------------------------------------------------------
// LinearSelfAttentionBlock  (B=4, C=512, L=4096, H=8, DH=64, MLP=2048)
// Round 3: GEMMs via mma.sync.m16n8k8.tf32 (baseline-PTX tensor path;
// tcgen05 unavailable: harness builds compute_103, not compute_103a).
// ---------------------------------------------------------------------------

constexpr int NB   = 4;
constexpr int NC   = 512;
constexpr int NL   = 4096;
constexpr int NH   = 8;
constexpr int NDH  = 64;
constexpr int NMLP = 2048;
constexpr int NM   = NB * NL;          // 16384 rows

// ------------------------- scratch (device globals) ------------------------
__device__ float g_xf   [NM * NC];
__device__ float g_Q    [NM * NC];
__device__ float g_K    [NM * NC];
__device__ float g_V    [NM * NC];
__device__ float g_phiQ [NM * NC];
__device__ float g_phiK [NM * NC];
__device__ float g_attn [NM * NC];
__device__ float g_aln  [NM * NC];
__device__ float g_res  [NM * NC];
__device__ float g_hid  [NM * NMLP];
__device__ float g_probe[NB * NC];
__device__ float g_score[NB * NH * NL];
__device__ float g_bot  [NB * NH * NL];
__device__ float g_s0   [NB * NH];
__device__ float g_kv   [NB * NH * NDH * NDH];
__device__ float g_ksum [NB * NH * NDH];
// transposed weights (Bt[n,k] = W[k,n])
__device__ float g_WqT [NC * NC];
__device__ float g_WkT [NC * NC];
__device__ float g_WvT [NC * NC];
__device__ float g_WkqT[NC * NC];
__device__ float g_WkkT[NC * NC];
__device__ float g_W1T [NC * NMLP];
__device__ float g_W2T [NMLP * NC];

// ------------------------- helpers -----------------------------------------
__device__ __forceinline__ uint32_t f2tf32(float x) {
    uint32_t r; asm("cvt.rna.tf32.f32 %0, %1;" : "=r"(r) : "f"(x)); return r;
}

__device__ __forceinline__ void mma_tf32(float& d0, float& d1, float& d2, float& d3,
                                         uint32_t a0, uint32_t a1, uint32_t a2, uint32_t a3,
                                         uint32_t b0, uint32_t b1)
{
    asm volatile(
        "mma.sync.aligned.m16n8k8.row.col.f32.tf32.tf32.f32 "
        "{%0,%1,%2,%3}, {%4,%5,%6,%7}, {%8,%9}, {%0,%1,%2,%3};"
        : "+f"(d0), "+f"(d1), "+f"(d2), "+f"(d3)
        : "r"(a0), "r"(a1), "r"(a2), "r"(a3), "r"(b0), "r"(b1));
}

// ------------------------- tensor-core GEMM  D = A[M,K] * Bt[N,K]^T --------
// EPI: 0 = +bias ; 1 = tanh(+bias)+1 ; 2 = gelu_exact(+bias) ; 3 = +bias+resid
// Tile 128x128, BK=32, 256 threads (8 warps, 2x4 -> 64x32 warp tiles).
constexpr int GSMEM = 2 * 32768;       // 2 stages x (16KB A + 16KB B)

template <int EPI>
__global__ void __launch_bounds__(256, 1)
gemm_mma(const float* __restrict__ A, const float* __restrict__ Bt,
         const float* __restrict__ bias, float* __restrict__ Out,
         int M, int N, int K, const float* __restrict__ resid)
{
    extern __shared__ char smem[];
    const int tid  = threadIdx.x;
    const int lane = tid & 31, wid = tid >> 5;
    const int wrow = (wid >> 2) * 64;        // 0 or 64
    const int wcol = (wid & 3) * 32;         // 0,32,64,96
    const int r = lane >> 2, c = lane & 3;
    const int br0 = blockIdx.y * 128, bc0 = blockIdx.x * 128;

    const float* Ab = A  + (size_t)br0 * K;
    const float* Bb = Bt + (size_t)bc0 * K;

    float acc[4][4][4];
    #pragma unroll
    for (int i = 0; i < 4; i++)
        #pragma unroll
        for (int j = 0; j < 4; j++)
            #pragma unroll
            for (int q = 0; q < 4; q++) acc[i][j][q] = 0.f;

    // staging coordinates: idx = tid + i*256 ; row = idx>>3 ; g = idx&7
    int srow[4], sgg[4];
    #pragma unroll
    for (int i = 0; i < 4; i++) {
        int idx = tid + i * 256;
        srow[i] = idx >> 3;
        sgg[i]  = idx & 7;
    }

    float4 pa[4], pb[4];
    const int nk = K >> 5;

    // prefetch chunk 0
    #pragma unroll
    for (int i = 0; i < 4; i++) {
        pa[i] = *reinterpret_cast<const float4*>(Ab + (size_t)srow[i] * K + sgg[i] * 4);
        pb[i] = *reinterpret_cast<const float4*>(Bb + (size_t)srow[i] * K + sgg[i] * 4);
    }

    for (int ch = 0; ch < nk; ch++) {
        char* sA = smem + (ch & 1) * 32768;
        char* sB = sA + 16384;
        // cvt + store staged tile (swizzled: 16B chunk ^= row&7)
        #pragma unroll
        for (int i = 0; i < 4; i++) {
            uint32_t sw = ((uint32_t)(sgg[i] ^ (srow[i] & 7)) << 4) + (uint32_t)srow[i] * 128u;
            uint4 ua = {f2tf32(pa[i].x), f2tf32(pa[i].y), f2tf32(pa[i].z), f2tf32(pa[i].w)};
            uint4 ub = {f2tf32(pb[i].x), f2tf32(pb[i].y), f2tf32(pb[i].z), f2tf32(pb[i].w)};
            *reinterpret_cast<uint4*>(sA + sw) = ua;
            *reinterpret_cast<uint4*>(sB + sw) = ub;
        }
        __syncthreads();

        // prefetch next chunk (latency hidden by compute below)
        if (ch + 1 < nk) {
            int k0 = (ch + 1) << 5;
            #pragma unroll
            for (int i = 0; i < 4; i++) {
                pa[i] = *reinterpret_cast<const float4*>(Ab + (size_t)srow[i] * K + k0 + sgg[i] * 4);
                pb[i] = *reinterpret_cast<const float4*>(Bb + (size_t)srow[i] * K + k0 + sgg[i] * 4);
            }
        }

        // compute: 4 k-steps of m16n8k8
        #pragma unroll
        for (int ks = 0; ks < 4; ks++) {
            const uint32_t ch0 = (uint32_t)((2 * ks) ^ r) << 4;
            const uint32_t ch1 = (uint32_t)((2 * ks + 1) ^ r) << 4;
            uint32_t afr[4][4], bfr[4][2];
            #pragma unroll
            for (int mt = 0; mt < 4; mt++) {
                uint32_t row0 = (uint32_t)(wrow + mt * 16 + r) * 128u;
                uint32_t row8 = row0 + 8u * 128u;
                afr[mt][0] = *reinterpret_cast<const uint32_t*>(sA + row0 + ch0 + c * 4);
                afr[mt][1] = *reinterpret_cast<const uint32_t*>(sA + row8 + ch0 + c * 4);
                afr[mt][2] = *reinterpret_cast<const uint32_t*>(sA + row0 + ch1 + c * 4);
                afr[mt][3] = *reinterpret_cast<const uint32_t*>(sA + row8 + ch1 + c * 4);
            }
            #pragma unroll
            for (int nt = 0; nt < 4; nt++) {
                uint32_t nrow = (uint32_t)(wcol + nt * 8 + r) * 128u;
                bfr[nt][0] = *reinterpret_cast<const uint32_t*>(sB + nrow + ch0 + c * 4);
                bfr[nt][1] = *reinterpret_cast<const uint32_t*>(sB + nrow + ch1 + c * 4);
            }
            #pragma unroll
            for (int mt = 0; mt < 4; mt++)
                #pragma unroll
                for (int nt = 0; nt < 4; nt++)
                    mma_tf32(acc[mt][nt][0], acc[mt][nt][1], acc[mt][nt][2], acc[mt][nt][3],
                             afr[mt][0], afr[mt][1], afr[mt][2], afr[mt][3],
                             bfr[nt][0], bfr[nt][1]);
        }
        __syncthreads();
    }

    // ------------------------- epilogue -------------------------
    #pragma unroll
    for (int mt = 0; mt < 4; mt++) {
        int row0 = br0 + wrow + mt * 16 + r;
        #pragma unroll
        for (int half = 0; half < 2; half++) {
            int row = row0 + half * 8;
            size_t ro = (size_t)row * N;
            #pragma unroll
            for (int nt = 0; nt < 4; nt++) {
                int col = bc0 + wcol + nt * 8 + c * 2;
                float v0 = acc[mt][nt][half * 2 + 0] + bias[col];
                float v1 = acc[mt][nt][half * 2 + 1] + bias[col + 1];
                if (EPI == 1) {
                    v0 = tanhf(v0) + 1.0f;
                    v1 = tanhf(v1) + 1.0f;
                } else if (EPI == 2) {
                    v0 = 0.5f * v0 * (1.0f + erff(v0 * 0.70710678118654752f));
                    v1 = 0.5f * v1 * (1.0f + erff(v1 * 0.70710678118654752f));
                } else if (EPI == 3) {
                    v0 += resid[ro + col];
                    v1 += resid[ro + col + 1];
                }
                float2 o = {v0, v1};
                *reinterpret_cast<float2*>(Out + ro + col) = o;
            }
        }
    }
}

// ------------------------- weight transpose Wt[n,k] = W[k,n] ---------------
__global__ void wtrans_kernel(const float* __restrict__ W, float* __restrict__ Wt,
                              int R, int Cc)
{
    __shared__ float t[32][33];
    int r0 = blockIdx.y * 32, c0 = blockIdx.x * 32;
    #pragma unroll
    for (int i = threadIdx.y; i < 32; i += 8)
        t[i][threadIdx.x] = W[(size_t)(r0 + i) * Cc + c0 + threadIdx.x];
    __syncthreads();
    #pragma unroll
    for (int i = threadIdx.y; i < 32; i += 8)
        Wt[(size_t)(c0 + i) * R + r0 + threadIdx.x] = t[threadIdx.x][i];
}

// ------------------------- transpose x[B,C,L] -> xf[B,L,C] -----------------
__global__ void transpose_in_kernel(const float* __restrict__ x, float* __restrict__ xf)
{
    __shared__ float tile[32][33];
    int b  = blockIdx.z;
    int l0 = blockIdx.x * 32, c0 = blockIdx.y * 32;
    const float* xb = x + (size_t)b * NC * NL;
    #pragma unroll
    for (int i = threadIdx.y; i < 32; i += 8)
        tile[i][threadIdx.x] = xb[(size_t)(c0 + i) * NL + l0 + threadIdx.x];
    __syncthreads();
    float* xfb = xf + (size_t)b * NL * NC;
    #pragma unroll
    for (int i = threadIdx.y; i < 32; i += 8)
        xfb[(size_t)(l0 + i) * NC + c0 + threadIdx.x] = tile[threadIdx.x][i];
}

// --------------- final: out[b,c,l] = res[b,l,c] + x[b,c,l] -----------------
__global__ void final_kernel(const float* __restrict__ res, const float* __restrict__ x,
                             float* __restrict__ out)
{
    __shared__ float tile[32][33];
    int b  = blockIdx.z;
    int l0 = blockIdx.x * 32, c0 = blockIdx.y * 32;
    const float* rb = res + (size_t)b * NL * NC;
    #pragma unroll
    for (int i = threadIdx.y; i < 32; i += 8)
        tile[i][threadIdx.x] = rb[(size_t)(l0 + i) * NC + c0 + threadIdx.x];
    __syncthreads();
    const float* xb = x + (size_t)b * NC * NL;
    float*       ob = out + (size_t)b * NC * NL;
    #pragma unroll
    for (int i = threadIdx.y; i < 32; i += 8) {
        size_t idx = (size_t)(c0 + i) * NL + l0 + threadIdx.x;
        ob[idx] = tile[threadIdx.x][i] + xb[idx];
    }
}

// ------------------------- layernorm over rows of 512 ----------------------
__global__ void layernorm_kernel(const float* __restrict__ in, float* __restrict__ out,
                                 const float* __restrict__ gamma, const float* __restrict__ beta)
{
    int row = blockIdx.x;
    int tid = threadIdx.x;                      // 128 threads, 4 floats each
    const float4 v = reinterpret_cast<const float4*>(in + (size_t)row * NC)[tid];
    __shared__ float sh[4];

    float s = v.x + v.y + v.z + v.w;
    #pragma unroll
    for (int o = 16; o > 0; o >>= 1) s += __shfl_xor_sync(0xffffffffu, s, o);
    if ((tid & 31) == 0) sh[tid >> 5] = s;
    __syncthreads();
    float mean = (sh[0] + sh[1] + sh[2] + sh[3]) * (1.0f / NC);
    __syncthreads();

    float dx = v.x - mean, dy = v.y - mean, dz = v.z - mean, dw = v.w - mean;
    float q = dx * dx + dy * dy + dz * dz + dw * dw;
    #pragma unroll
    for (int o = 16; o > 0; o >>= 1) q += __shfl_xor_sync(0xffffffffu, q, o);
    if ((tid & 31) == 0) sh[tid >> 5] = q;
    __syncthreads();
    float var = (sh[0] + sh[1] + sh[2] + sh[3]) * (1.0f / NC);
    float inv = rsqrtf(var + 1e-5f);

    float4 g  = reinterpret_cast<const float4*>(gamma)[tid];
    float4 bb = reinterpret_cast<const float4*>(beta)[tid];
    float4 o4;
    o4.x = dx * inv * g.x + bb.x;
    o4.y = dy * inv * g.y + bb.y;
    o4.z = dz * inv * g.z + bb.z;
    o4.w = dw * inv * g.w + bb.w;
    reinterpret_cast<float4*>(out + (size_t)row * NC)[tid] = o4;
}

// ------------------------- misc small kernels ------------------------------
__global__ void zero_kernel(float* __restrict__ p, int n)
{
    int i = blockIdx.x * blockDim.x + threadIdx.x;
    if (i < n) p[i] = 0.f;
}

__global__ void probe_kernel(const float* __restrict__ Q, float* __restrict__ probe)
{
    int b = blockIdx.x, chunk = blockIdx.y;
    int c = threadIdx.x;                        // 512 threads
    float s = 0.f;
    size_t base = ((size_t)b * NL + (size_t)chunk * 128) * NC + c;
    for (int i = 0; i < 128; i++) s += Q[base + (size_t)i * NC];
    atomicAdd(&probe[b * NC + c], s);
}

__global__ void headdot_kernel(const float* __restrict__ rows, const float* __restrict__ vecs,
                               float* __restrict__ out, float scale)
{
    int warp = (blockIdx.x * blockDim.x + threadIdx.x) >> 5;
    int lane = threadIdx.x & 31;
    if (warp >= NB * NL) return;
    int b = warp / NL, l = warp % NL;
    const float* row = rows + (size_t)warp * NC;
    const float* vec = vecs + (size_t)b * NC;
    float p[8];
    #pragma unroll
    for (int h = 0; h < 8; h++) p[h] = 0.f;
    #pragma unroll
    for (int j = 0; j < 16; j++) {
        int c = lane + 32 * j;
        p[j >> 1] += row[c] * vec[c];
    }
    #pragma unroll
    for (int h = 0; h < 8; h++) {
        float v = p[h];
        #pragma unroll
        for (int o = 16; o > 0; o >>= 1) v += __shfl_xor_sync(0xffffffffu, v, o);
        p[h] = v;
    }
    if (lane == 0) {
        #pragma unroll
        for (int h = 0; h < 8; h++)
            out[((size_t)b * NH + h) * NL + l] = p[h] * scale;
    }
}

__global__ void softmax_kernel(float* __restrict__ score, float* __restrict__ s0)
{
    int bh = blockIdx.x;
    float* s = score + (size_t)bh * NL;
    int tid = threadIdx.x;                      // 256 threads
    __shared__ float sh[8];
    __shared__ float bc2[2];

    float m = 0.0f;                             // includes zero-token score 0
    for (int i = tid; i < NL; i += 256) m = fmaxf(m, s[i]);
    #pragma unroll
    for (int o = 16; o > 0; o >>= 1) m = fmaxf(m, __shfl_xor_sync(0xffffffffu, m, o));
    if ((tid & 31) == 0) sh[tid >> 5] = m;
    __syncthreads();
    if (tid == 0) {
        float mm = sh[0];
        for (int i = 1; i < 8; i++) mm = fmaxf(mm, sh[i]);
        bc2[0] = mm;
    }
    __syncthreads();
    m = bc2[0];

    float sum = 0.f;
    for (int i = tid; i < NL; i += 256) sum += expf(s[i] - m);
    #pragma unroll
    for (int o = 16; o > 0; o >>= 1) sum += __shfl_xor_sync(0xffffffffu, sum, o);
    if ((tid & 31) == 0) sh[tid >> 5] = sum;
    __syncthreads();
    if (tid == 0) {
        float t = expf(-m);                     // zero token
        for (int i = 0; i < 8; i++) t += sh[i];
        bc2[1] = 1.0f / t;
    }
    __syncthreads();
    float inv = bc2[1];
    for (int i = tid; i < NL; i += 256) s[i] = expf(s[i] - m) * inv;
    if (tid == 0) s0[bh] = expf(-m) * inv;
}

__global__ void kv_kernel(const float* __restrict__ phiK, const float* __restrict__ V,
                          const float* __restrict__ score, float* __restrict__ kv,
                          float* __restrict__ ksum)
{
    int bh = blockIdx.x, b = bh >> 3, h = bh & 7;
    int l0 = blockIdx.y * (NL / 8);             // 512-row chunk
    __shared__ float pks[8][64];
    __shared__ float vs[8][64];
    int tid = threadIdx.x;
    int d0 = (tid >> 4) << 2;
    int e0 = (tid & 15) << 2;
    float acc[4][4];
    #pragma unroll
    for (int i = 0; i < 4; i++)
        #pragma unroll
        for (int j = 0; j < 4; j++) acc[i][j] = 0.f;
    float ks[4] = {0.f, 0.f, 0.f, 0.f};

    const size_t base = ((size_t)b * NL) * NC + (size_t)h * 64;
    const float* scb = score + (size_t)bh * NL;

    for (int lt = 0; lt < NL / 8; lt += 8) {
        #pragma unroll
        for (int s = 0; s < 2; s++) {
            int idx = tid + (s << 8);
            int r = idx >> 6, col = idx & 63;
            int l = l0 + lt + r;
            size_t off = base + (size_t)l * NC + col;
            pks[r][col] = phiK[off] * scb[l];
            vs[r][col]  = V[off];
        }
        __syncthreads();
        #pragma unroll
        for (int r = 0; r < 8; r++) {
            float4 pk = *reinterpret_cast<const float4*>(&pks[r][d0]);
            float4 vv = *reinterpret_cast<const float4*>(&vs[r][e0]);
            float pa[4] = {pk.x, pk.y, pk.z, pk.w};
            float va[4] = {vv.x, vv.y, vv.z, vv.w};
            #pragma unroll
            for (int i = 0; i < 4; i++)
                #pragma unroll
                for (int j = 0; j < 4; j++) acc[i][j] += pa[i] * va[j];
            if (e0 == 0) {
                #pragma unroll
                for (int i = 0; i < 4; i++) ks[i] += pa[i];
            }
        }
        __syncthreads();
    }
    float* kvb = kv + (size_t)bh * 4096;
    #pragma unroll
    for (int i = 0; i < 4; i++)
        #pragma unroll
        for (int j = 0; j < 4; j++)
            atomicAdd(&kvb[(d0 + i) * 64 + e0 + j], acc[i][j]);
    if (e0 == 0) {
        #pragma unroll
        for (int i = 0; i < 4; i++) atomicAdd(&ksum[bh * 64 + d0 + i], ks[i]);
    }
}

__global__ void ksum_s0_kernel(const float* __restrict__ bkk, const float* __restrict__ s0,
                               float* __restrict__ ksum)
{
    int bh = blockIdx.x, h = bh & 7;
    int d = threadIdx.x;
    ksum[bh * 64 + d] += s0[bh] * (tanhf(bkk[h * 64 + d]) + 1.0f);
}

__global__ void attnout_kernel(const float* __restrict__ phiQ, const float* __restrict__ kv,
                               const float* __restrict__ bottom, float* __restrict__ out)
{
    int bh = blockIdx.y, b = bh >> 3, h = bh & 7;
    int ltile = blockIdx.x;
    __shared__ float kvs[4096];
    __shared__ float pqs[4][64];
    int tid = threadIdx.x;
    const float* kvb = kv + (size_t)bh * 4096;
    for (int i = tid; i < 4096; i += 256) kvs[i] = kvb[i];
    int rr = tid >> 6, e = tid & 63;
    size_t rowc = (size_t)b * NL + (size_t)ltile * 64;
    for (int r0 = 0; r0 < 64; r0 += 4) {
        __syncthreads();
        pqs[rr][e] = phiQ[(rowc + r0 + rr) * NC + h * 64 + e];
        __syncthreads();
        float num = 0.f;
        #pragma unroll
        for (int d = 0; d < 64; d++) num += pqs[rr][d] * kvs[d * 64 + e];
        int l = ltile * 64 + r0 + rr;
        float bot = bottom[(size_t)bh * NL + l] + 1e-6f;
        out[(rowc + r0 + rr) * NC + h * 64 + e] = num / bot;
    }
}

// ---------------------------------------------------------------------------
extern "C" void kernel_launch(void* const* d_in, const int* in_sizes, int n_in,
                              void* d_out, int out_size)
{
    (void)in_sizes; (void)n_in; (void)out_size;
    const float* x      = (const float*)d_in[0];
    const float* Wq     = (const float*)d_in[1];
    const float* bq     = (const float*)d_in[2];
    const float* gq     = (const float*)d_in[3];
    const float* betaq  = (const float*)d_in[4];
    const float* Wk     = (const float*)d_in[5];
    const float* bk     = (const float*)d_in[6];
    const float* gk     = (const float*)d_in[7];
    const float* betak  = (const float*)d_in[8];
    const float* Wv     = (const float*)d_in[9];
    const float* bv     = (const float*)d_in[10];
    const float* gv     = (const float*)d_in[11];
    const float* betav  = (const float*)d_in[12];
    const float* Wkq    = (const float*)d_in[13];
    const float* bkq    = (const float*)d_in[14];
    const float* Wkk    = (const float*)d_in[15];
    const float* bkk    = (const float*)d_in[16];
    const float* gat    = (const float*)d_in[17];
    const float* bat    = (const float*)d_in[18];
    const float* W1     = (const float*)d_in[19];
    const float* b1     = (const float*)d_in[20];
    const float* W2     = (const float*)d_in[21];
    const float* b2     = (const float*)d_in[22];
    float* out = (float*)d_out;

    float *xf, *Q, *K, *V, *phiQ, *phiK, *attn, *aln, *res, *hid;
    float *probe, *score, *bot, *s0, *kv, *ksum;
    float *WqT, *WkT, *WvT, *WkqT, *WkkT, *W1T, *W2T;
    cudaGetSymbolAddress((void**)&xf,    g_xf);
    cudaGetSymbolAddress((void**)&Q,     g_Q);
    cudaGetSymbolAddress((void**)&K,     g_K);
    cudaGetSymbolAddress((void**)&V,     g_V);
    cudaGetSymbolAddress((void**)&phiQ,  g_phiQ);
    cudaGetSymbolAddress((void**)&phiK,  g_phiK);
    cudaGetSymbolAddress((void**)&attn,  g_attn);
    cudaGetSymbolAddress((void**)&aln,   g_aln);
    cudaGetSymbolAddress((void**)&res,   g_res);
    cudaGetSymbolAddress((void**)&hid,   g_hid);
    cudaGetSymbolAddress((void**)&probe, g_probe);
    cudaGetSymbolAddress((void**)&score, g_score);
    cudaGetSymbolAddress((void**)&bot,   g_bot);
    cudaGetSymbolAddress((void**)&s0,    g_s0);
    cudaGetSymbolAddress((void**)&kv,    g_kv);
    cudaGetSymbolAddress((void**)&ksum,  g_ksum);
    cudaGetSymbolAddress((void**)&WqT,   g_WqT);
    cudaGetSymbolAddress((void**)&WkT,   g_WkT);
    cudaGetSymbolAddress((void**)&WvT,   g_WvT);
    cudaGetSymbolAddress((void**)&WkqT,  g_WkqT);
    cudaGetSymbolAddress((void**)&WkkT,  g_WkkT);
    cudaGetSymbolAddress((void**)&W1T,   g_W1T);
    cudaGetSymbolAddress((void**)&W2T,   g_W2T);

    cudaFuncSetAttribute(gemm_mma<0>, cudaFuncAttributeMaxDynamicSharedMemorySize, GSMEM);
    cudaFuncSetAttribute(gemm_mma<1>, cudaFuncAttributeMaxDynamicSharedMemorySize, GSMEM);
    cudaFuncSetAttribute(gemm_mma<2>, cudaFuncAttributeMaxDynamicSharedMemorySize, GSMEM);
    cudaFuncSetAttribute(gemm_mma<3>, cudaFuncAttributeMaxDynamicSharedMemorySize, GSMEM);

    dim3 tgrid(NL / 32, NC / 32, NB), tblk(32, 8);
    transpose_in_kernel<<<tgrid, tblk>>>(x, xf);

    dim3 wt512(NC / 32, NC / 32);
    wtrans_kernel<<<wt512, tblk>>>(Wq,  WqT,  NC, NC);
    wtrans_kernel<<<wt512, tblk>>>(Wk,  WkT,  NC, NC);
    wtrans_kernel<<<wt512, tblk>>>(Wv,  WvT,  NC, NC);
    wtrans_kernel<<<wt512, tblk>>>(Wkq, WkqT, NC, NC);
    wtrans_kernel<<<wt512, tblk>>>(Wkk, WkkT, NC, NC);
    wtrans_kernel<<<dim3(NMLP / 32, NC / 32), tblk>>>(W1, W1T, NC, NMLP);
    wtrans_kernel<<<dim3(NC / 32, NMLP / 32), tblk>>>(W2, W2T, NMLP, NC);

    dim3 gC(NC / 128, NM / 128);                // (4, 128)
    gemm_mma<0><<<gC, 256, GSMEM>>>(xf, WqT, bq, Q, NM, NC, NC, nullptr);
    gemm_mma<0><<<gC, 256, GSMEM>>>(xf, WkT, bk, K, NM, NC, NC, nullptr);
    gemm_mma<0><<<gC, 256, GSMEM>>>(xf, WvT, bv, V, NM, NC, NC, nullptr);

    layernorm_kernel<<<NM, 128>>>(Q, Q, gq, betaq);
    layernorm_kernel<<<NM, 128>>>(K, K, gk, betak);
    layernorm_kernel<<<NM, 128>>>(V, V, gv, betav);

    zero_kernel<<<(NB * NC + 255) / 256, 256>>>(probe, NB * NC);
    zero_kernel<<<(NB * NH * NDH * NDH + 255) / 256, 256>>>(kv, NB * NH * NDH * NDH);
    zero_kernel<<<(NB * NH * NDH + 255) / 256, 256>>>(ksum, NB * NH * NDH);

    probe_kernel<<<dim3(NB, 32), 512>>>(Q, probe);

    gemm_mma<1><<<gC, 256, GSMEM>>>(Q, WkqT, bkq, phiQ, NM, NC, NC, nullptr);
    gemm_mma<1><<<gC, 256, GSMEM>>>(K, WkkT, bkk, phiK, NM, NC, NC, nullptr);

    headdot_kernel<<<(NB * NL) / 8, 256>>>(K, probe, score, 1.0f / ((float)NL * 8.0f));
    softmax_kernel<<<NB * NH, 256>>>(score, s0);

    kv_kernel<<<dim3(NB * NH, 8), 256>>>(phiK, V, score, kv, ksum);
    ksum_s0_kernel<<<NB * NH, 64>>>(bkk, s0, ksum);

    headdot_kernel<<<(NB * NL) / 8, 256>>>(phiQ, ksum, bot, 1.0f);
    attnout_kernel<<<dim3(NL / 64, NB * NH), 256>>>(phiQ, kv, bot, attn);

    layernorm_kernel<<<NM, 128>>>(attn, aln, gat, bat);

    dim3 gUp(NMLP / 128, NM / 128);             // (16, 128)
    gemm_mma<2><<<gUp, 256, GSMEM>>>(aln, W1T, b1, hid, NM, NMLP, NC, nullptr);
    gemm_mma<3><<<gC, 256, GSMEM>>>(hid, W2T, b2, res, NM, NC, NMLP, aln);

    final_kernel<<<tgrid, tblk>>>(res, x, out);
}

// round 4
// speedup vs baseline: 3.2265x; 1.3148x over previous
#include <cuda_runtime.h>
#include <cuda_fp16.h>
#include <cstdint>

// ---------------------------------------------------------------------------
// LinearSelfAttentionBlock  (B=4, C=512, L=4096, H=8, DH=64, MLP=2048)
// Round 4: fp16 mma.sync.m16n8k16 (same 10-bit mantissa as tf32, 2x rate),
// ldmatrix fragments, cp.async fp16 weights, 2-stage pipeline.
// ---------------------------------------------------------------------------

constexpr int NB   = 4;
constexpr int NC   = 512;
constexpr int NL   = 4096;
constexpr int NH   = 8;
constexpr int NDH  = 64;
constexpr int NMLP = 2048;
constexpr int NM   = NB * NL;          // 16384 rows

// ------------------------- scratch (device globals) ------------------------
__device__ float g_xf   [NM * NC];
__device__ float g_Q    [NM * NC];
__device__ float g_K    [NM * NC];
__device__ float g_V    [NM * NC];
__device__ float g_phiQ [NM * NC];
__device__ float g_phiK [NM * NC];
__device__ float g_attn [NM * NC];
__device__ float g_aln  [NM * NC];
__device__ float g_res  [NM * NC];
__device__ float g_hid  [NM * NMLP];
__device__ float g_probe[NB * NC];
__device__ float g_score[NB * NH * NL];
__device__ float g_bot  [NB * NH * NL];
__device__ float g_s0   [NB * NH];
__device__ float g_kv   [NB * NH * NDH * NDH];
__device__ float g_ksum [NB * NH * NDH];
// fp16 transposed weights (Bt[n,k] = W[k,n])
__device__ __align__(16) __half g_WqT [NC * NC];
__device__ __align__(16) __half g_WkT [NC * NC];
__device__ __align__(16) __half g_WvT [NC * NC];
__device__ __align__(16) __half g_WkqT[NC * NC];
__device__ __align__(16) __half g_WkkT[NC * NC];
__device__ __align__(16) __half g_W1T [NC * NMLP];
__device__ __align__(16) __half g_W2T [NMLP * NC];

// ------------------------- helpers -----------------------------------------
__device__ __forceinline__ uint32_t smem_u32(const void* p) {
    uint32_t a;
    asm("{ .reg .u64 t; cvta.to.shared.u64 t, %1; cvt.u32.u64 %0, t; }" : "=r"(a) : "l"(p));
    return a;
}
__device__ __forceinline__ uint32_t f2h2(float a, float b) {
    __half2 h = __float22half2_rn(make_float2(a, b));
    return *reinterpret_cast<uint32_t*>(&h);
}

#define CP_ASYNC16(dst, src) \
    asm volatile("cp.async.cg.shared.global [%0], [%1], 16;" :: "r"(dst), "l"(src))
#define CP_COMMIT() asm volatile("cp.async.commit_group;" ::: "memory")
#define CP_WAIT0()  asm volatile("cp.async.wait_group 0;" ::: "memory")

#define LDSM_X4(r0, r1, r2, r3, a)                                             \
    asm volatile("ldmatrix.sync.aligned.m8n8.x4.shared.b16 {%0,%1,%2,%3}, [%4];" \
                 : "=r"(r0), "=r"(r1), "=r"(r2), "=r"(r3) : "r"(a))
#define LDSM_X2(r0, r1, a)                                                     \
    asm volatile("ldmatrix.sync.aligned.m8n8.x2.shared.b16 {%0,%1}, [%2];"     \
                 : "=r"(r0), "=r"(r1) : "r"(a))

__device__ __forceinline__ void mma_f16(float& d0, float& d1, float& d2, float& d3,
                                        uint32_t a0, uint32_t a1, uint32_t a2, uint32_t a3,
                                        uint32_t b0, uint32_t b1)
{
    asm volatile(
        "mma.sync.aligned.m16n8k16.row.col.f32.f16.f16.f32 "
        "{%0,%1,%2,%3}, {%4,%5,%6,%7}, {%8,%9}, {%0,%1,%2,%3};"
        : "+f"(d0), "+f"(d1), "+f"(d2), "+f"(d3)
        : "r"(a0), "r"(a1), "r"(a2), "r"(a3), "r"(b0), "r"(b1));
}

// ------------------------- tensor-core GEMM  D = A[M,K] * Bt[N,K]^T --------
// EPI: 0 = +bias ; 1 = tanh(+bias)+1 ; 2 = gelu_exact(+bias) ; 3 = +bias+resid
// Tile 128x128, BK=64, 256 threads (8 warps, 2x4 -> 64x32 warp tiles).
// SMEM per stage: A 16KB + B 16KB; 2 stages = 64KB. Rows are 128B (64 halves),
// swizzled in 16B groups: g' = g ^ (row & 7).
constexpr int GSMEM = 65536;

template <int EPI>
__global__ void __launch_bounds__(256, 1)
gemm_mma(const float* __restrict__ A, const __half* __restrict__ Bt,
         const float* __restrict__ bias, float* __restrict__ Out,
         int M, int N, int K, const float* __restrict__ resid)
{
    extern __shared__ char smem[];
    const uint32_t sbu = smem_u32(smem);
    const int tid  = threadIdx.x;
    const int lane = tid & 31, wid = tid >> 5;
    const int wrow = (wid >> 2) * 64;        // 0 or 64
    const int wcol = (wid & 3) * 32;         // 0,32,64,96
    const int br0 = blockIdx.y * 128, bc0 = blockIdx.x * 128;

    const float*  Ab = A  + (size_t)br0 * K;
    const __half* Bb = Bt + (size_t)bc0 * K;

    float acc[4][4][4];
    #pragma unroll
    for (int i = 0; i < 4; i++)
        #pragma unroll
        for (int j = 0; j < 4; j++)
            #pragma unroll
            for (int q = 0; q < 4; q++) acc[i][j][q] = 0.f;

    // staging indices: idx = tid + i*256 in [0,1024); row = idx>>3, g = idx&7
    int srow[4], sg[4];
    uint32_t ssw[4];
    #pragma unroll
    for (int i = 0; i < 4; i++) {
        int idx = tid + i * 256;
        srow[i] = idx >> 3;
        sg[i]   = idx & 7;
        ssw[i]  = (uint32_t)srow[i] * 128u + ((uint32_t)(sg[i] ^ (srow[i] & 7)) << 4);
    }

    const int nk = K >> 6;

    // prologue: cp.async B(0) into stage 0, load+cvt A(0)
    #pragma unroll
    for (int i = 0; i < 4; i++)
        CP_ASYNC16(sbu + 16384u + ssw[i], Bb + (size_t)srow[i] * K + sg[i] * 8);
    CP_COMMIT();

    uint4 pa[4];
    #pragma unroll
    for (int i = 0; i < 4; i++) {
        const float4* p = reinterpret_cast<const float4*>(Ab + (size_t)srow[i] * K + sg[i] * 8);
        float4 f0 = p[0], f1 = p[1];
        pa[i] = make_uint4(f2h2(f0.x, f0.y), f2h2(f0.z, f0.w),
                           f2h2(f1.x, f1.y), f2h2(f1.z, f1.w));
    }

    for (int ch = 0; ch < nk; ch++) {
        const uint32_t stoff = (uint32_t)(ch & 1) * 32768u;
        // store A tile
        #pragma unroll
        for (int i = 0; i < 4; i++)
            *reinterpret_cast<uint4*>(smem + stoff + ssw[i]) = pa[i];
        CP_WAIT0();
        __syncthreads();

        // issue next chunk's loads (overlap with compute)
        if (ch + 1 < nk) {
            const int k0 = (ch + 1) << 6;
            const uint32_t nst = (uint32_t)((ch + 1) & 1) * 32768u;
            #pragma unroll
            for (int i = 0; i < 4; i++)
                CP_ASYNC16(sbu + nst + 16384u + ssw[i],
                           Bb + (size_t)srow[i] * K + k0 + sg[i] * 8);
            CP_COMMIT();
            #pragma unroll
            for (int i = 0; i < 4; i++) {
                const float4* p = reinterpret_cast<const float4*>(
                    Ab + (size_t)srow[i] * K + k0 + sg[i] * 8);
                float4 f0 = p[0], f1 = p[1];
                pa[i] = make_uint4(f2h2(f0.x, f0.y), f2h2(f0.z, f0.w),
                                   f2h2(f1.x, f1.y), f2h2(f1.z, f1.w));
            }
        }

        // compute 4 k16 steps
        const uint32_t sAu = sbu + stoff;
        const uint32_t sBu = sAu + 16384u;
        #pragma unroll
        for (int ks = 0; ks < 4; ks++) {
            uint32_t afr[4][4], bfr[4][2];
            #pragma unroll
            for (int mt = 0; mt < 4; mt++) {
                int row = wrow + mt * 16 + (lane & 15);
                uint32_t g = 2u * ks + (uint32_t)(lane >> 4);
                uint32_t ad = sAu + (uint32_t)row * 128u + ((g ^ (uint32_t)(row & 7)) << 4);
                LDSM_X4(afr[mt][0], afr[mt][1], afr[mt][2], afr[mt][3], ad);
            }
            #pragma unroll
            for (int nt = 0; nt < 4; nt++) {
                int row = wcol + nt * 8 + (lane & 7);
                uint32_t g = 2u * ks + (uint32_t)((lane >> 3) & 1);
                uint32_t bd = sBu + (uint32_t)row * 128u + ((g ^ (uint32_t)(row & 7)) << 4);
                LDSM_X2(bfr[nt][0], bfr[nt][1], bd);
            }
            #pragma unroll
            for (int mt = 0; mt < 4; mt++)
                #pragma unroll
                for (int nt = 0; nt < 4; nt++)
                    mma_f16(acc[mt][nt][0], acc[mt][nt][1], acc[mt][nt][2], acc[mt][nt][3],
                            afr[mt][0], afr[mt][1], afr[mt][2], afr[mt][3],
                            bfr[nt][0], bfr[nt][1]);
        }
    }

    // ------------------------- epilogue -------------------------
    const int r = lane >> 2, c = lane & 3;
    #pragma unroll
    for (int mt = 0; mt < 4; mt++) {
        int row0 = br0 + wrow + mt * 16 + r;
        #pragma unroll
        for (int half = 0; half < 2; half++) {
            int row = row0 + half * 8;
            size_t ro = (size_t)row * N;
            #pragma unroll
            for (int nt = 0; nt < 4; nt++) {
                int col = bc0 + wcol + nt * 8 + c * 2;
                float v0 = acc[mt][nt][half * 2 + 0] + bias[col];
                float v1 = acc[mt][nt][half * 2 + 1] + bias[col + 1];
                if (EPI == 1) {
                    v0 = tanhf(v0) + 1.0f;
                    v1 = tanhf(v1) + 1.0f;
                } else if (EPI == 2) {
                    v0 = 0.5f * v0 * (1.0f + erff(v0 * 0.70710678118654752f));
                    v1 = 0.5f * v1 * (1.0f + erff(v1 * 0.70710678118654752f));
                } else if (EPI == 3) {
                    v0 += resid[ro + col];
                    v1 += resid[ro + col + 1];
                }
                float2 o = {v0, v1};
                *reinterpret_cast<float2*>(Out + ro + col) = o;
            }
        }
    }
}

// ------------------- weight transpose + fp16: Wt[n,k] = W[k,n] -------------
__global__ void wtrans_kernel(const float* __restrict__ W, __half* __restrict__ Wt,
                              int R, int Cc)
{
    __shared__ float t[32][33];
    int r0 = blockIdx.y * 32, c0 = blockIdx.x * 32;
    #pragma unroll
    for (int i = threadIdx.y; i < 32; i += 8)
        t[i][threadIdx.x] = W[(size_t)(r0 + i) * Cc + c0 + threadIdx.x];
    __syncthreads();
    #pragma unroll
    for (int i = threadIdx.y; i < 32; i += 8)
        Wt[(size_t)(c0 + i) * R + r0 + threadIdx.x] = __float2half_rn(t[threadIdx.x][i]);
}

// ------------------------- transpose x[B,C,L] -> xf[B,L,C] -----------------
__global__ void transpose_in_kernel(const float* __restrict__ x, float* __restrict__ xf)
{
    __shared__ float tile[32][33];
    int b  = blockIdx.z;
    int l0 = blockIdx.x * 32, c0 = blockIdx.y * 32;
    const float* xb = x + (size_t)b * NC * NL;
    #pragma unroll
    for (int i = threadIdx.y; i < 32; i += 8)
        tile[i][threadIdx.x] = xb[(size_t)(c0 + i) * NL + l0 + threadIdx.x];
    __syncthreads();
    float* xfb = xf + (size_t)b * NL * NC;
    #pragma unroll
    for (int i = threadIdx.y; i < 32; i += 8)
        xfb[(size_t)(l0 + i) * NC + c0 + threadIdx.x] = tile[threadIdx.x][i];
}

// --------------- final: out[b,c,l] = res[b,l,c] + x[b,c,l] -----------------
__global__ void final_kernel(const float* __restrict__ res, const float* __restrict__ x,
                             float* __restrict__ out)
{
    __shared__ float tile[32][33];
    int b  = blockIdx.z;
    int l0 = blockIdx.x * 32, c0 = blockIdx.y * 32;
    const float* rb = res + (size_t)b * NL * NC;
    #pragma unroll
    for (int i = threadIdx.y; i < 32; i += 8)
        tile[i][threadIdx.x] = rb[(size_t)(l0 + i) * NC + c0 + threadIdx.x];
    __syncthreads();
    const float* xb = x + (size_t)b * NC * NL;
    float*       ob = out + (size_t)b * NC * NL;
    #pragma unroll
    for (int i = threadIdx.y; i < 32; i += 8) {
        size_t idx = (size_t)(c0 + i) * NL + l0 + threadIdx.x;
        ob[idx] = tile[threadIdx.x][i] + xb[idx];
    }
}

// ------------------------- layernorm over rows of 512 ----------------------
__global__ void layernorm_kernel(const float* __restrict__ in, float* __restrict__ out,
                                 const float* __restrict__ gamma, const float* __restrict__ beta)
{
    int row = blockIdx.x;
    int tid = threadIdx.x;                      // 128 threads, 4 floats each
    const float4 v = reinterpret_cast<const float4*>(in + (size_t)row * NC)[tid];
    __shared__ float sh[4];

    float s = v.x + v.y + v.z + v.w;
    #pragma unroll
    for (int o = 16; o > 0; o >>= 1) s += __shfl_xor_sync(0xffffffffu, s, o);
    if ((tid & 31) == 0) sh[tid >> 5] = s;
    __syncthreads();
    float mean = (sh[0] + sh[1] + sh[2] + sh[3]) * (1.0f / NC);
    __syncthreads();

    float dx = v.x - mean, dy = v.y - mean, dz = v.z - mean, dw = v.w - mean;
    float q = dx * dx + dy * dy + dz * dz + dw * dw;
    #pragma unroll
    for (int o = 16; o > 0; o >>= 1) q += __shfl_xor_sync(0xffffffffu, q, o);
    if ((tid & 31) == 0) sh[tid >> 5] = q;
    __syncthreads();
    float var = (sh[0] + sh[1] + sh[2] + sh[3]) * (1.0f / NC);
    float inv = rsqrtf(var + 1e-5f);

    float4 g  = reinterpret_cast<const float4*>(gamma)[tid];
    float4 bb = reinterpret_cast<const float4*>(beta)[tid];
    float4 o4;
    o4.x = dx * inv * g.x + bb.x;
    o4.y = dy * inv * g.y + bb.y;
    o4.z = dz * inv * g.z + bb.z;
    o4.w = dw * inv * g.w + bb.w;
    reinterpret_cast<float4*>(out + (size_t)row * NC)[tid] = o4;
}

// ------------------------- misc small kernels ------------------------------
__global__ void zero_kernel(float* __restrict__ p, int n)
{
    int i = blockIdx.x * blockDim.x + threadIdx.x;
    if (i < n) p[i] = 0.f;
}

__global__ void probe_kernel(const float* __restrict__ Q, float* __restrict__ probe)
{
    int b = blockIdx.x, chunk = blockIdx.y;
    int c = threadIdx.x;                        // 512 threads
    float s = 0.f;
    size_t base = ((size_t)b * NL + (size_t)chunk * 128) * NC + c;
    for (int i = 0; i < 128; i++) s += Q[base + (size_t)i * NC];
    atomicAdd(&probe[b * NC + c], s);
}

__global__ void headdot_kernel(const float* __restrict__ rows, const float* __restrict__ vecs,
                               float* __restrict__ out, float scale)
{
    int warp = (blockIdx.x * blockDim.x + threadIdx.x) >> 5;
    int lane = threadIdx.x & 31;
    if (warp >= NB * NL) return;
    int b = warp / NL, l = warp % NL;
    const float* row = rows + (size_t)warp * NC;
    const float* vec = vecs + (size_t)b * NC;
    float p[8];
    #pragma unroll
    for (int h = 0; h < 8; h++) p[h] = 0.f;
    #pragma unroll
    for (int j = 0; j < 16; j++) {
        int c = lane + 32 * j;
        p[j >> 1] += row[c] * vec[c];
    }
    #pragma unroll
    for (int h = 0; h < 8; h++) {
        float v = p[h];
        #pragma unroll
        for (int o = 16; o > 0; o >>= 1) v += __shfl_xor_sync(0xffffffffu, v, o);
        p[h] = v;
    }
    if (lane == 0) {
        #pragma unroll
        for (int h = 0; h < 8; h++)
            out[((size_t)b * NH + h) * NL + l] = p[h] * scale;
    }
}

__global__ void softmax_kernel(float* __restrict__ score, float* __restrict__ s0)
{
    int bh = blockIdx.x;
    float* s = score + (size_t)bh * NL;
    int tid = threadIdx.x;                      // 256 threads
    __shared__ float sh[8];
    __shared__ float bc2[2];

    float m = 0.0f;                             // includes zero-token score 0
    for (int i = tid; i < NL; i += 256) m = fmaxf(m, s[i]);
    #pragma unroll
    for (int o = 16; o > 0; o >>= 1) m = fmaxf(m, __shfl_xor_sync(0xffffffffu, m, o));
    if ((tid & 31) == 0) sh[tid >> 5] = m;
    __syncthreads();
    if (tid == 0) {
        float mm = sh[0];
        for (int i = 1; i < 8; i++) mm = fmaxf(mm, sh[i]);
        bc2[0] = mm;
    }
    __syncthreads();
    m = bc2[0];

    float sum = 0.f;
    for (int i = tid; i < NL; i += 256) sum += expf(s[i] - m);
    #pragma unroll
    for (int o = 16; o > 0; o >>= 1) sum += __shfl_xor_sync(0xffffffffu, sum, o);
    if ((tid & 31) == 0) sh[tid >> 5] = sum;
    __syncthreads();
    if (tid == 0) {
        float t = expf(-m);                     // zero token
        for (int i = 0; i < 8; i++) t += sh[i];
        bc2[1] = 1.0f / t;
    }
    __syncthreads();
    float inv = bc2[1];
    for (int i = tid; i < NL; i += 256) s[i] = expf(s[i] - m) * inv;
    if (tid == 0) s0[bh] = expf(-m) * inv;
}

__global__ void kv_kernel(const float* __restrict__ phiK, const float* __restrict__ V,
                          const float* __restrict__ score, float* __restrict__ kv,
                          float* __restrict__ ksum)
{
    int bh = blockIdx.x, b = bh >> 3, h = bh & 7;
    int l0 = blockIdx.y * (NL / 8);             // 512-row chunk
    __shared__ float pks[8][64];
    __shared__ float vs[8][64];
    int tid = threadIdx.x;
    int d0 = (tid >> 4) << 2;
    int e0 = (tid & 15) << 2;
    float acc[4][4];
    #pragma unroll
    for (int i = 0; i < 4; i++)
        #pragma unroll
        for (int j = 0; j < 4; j++) acc[i][j] = 0.f;
    float ks[4] = {0.f, 0.f, 0.f, 0.f};

    const size_t base = ((size_t)b * NL) * NC + (size_t)h * 64;
    const float* scb = score + (size_t)bh * NL;

    for (int lt = 0; lt < NL / 8; lt += 8) {
        #pragma unroll
        for (int s = 0; s < 2; s++) {
            int idx = tid + (s << 8);
            int r = idx >> 6, col = idx & 63;
            int l = l0 + lt + r;
            size_t off = base + (size_t)l * NC + col;
            pks[r][col] = phiK[off] * scb[l];
            vs[r][col]  = V[off];
        }
        __syncthreads();
        #pragma unroll
        for (int r = 0; r < 8; r++) {
            float4 pk = *reinterpret_cast<const float4*>(&pks[r][d0]);
            float4 vv = *reinterpret_cast<const float4*>(&vs[r][e0]);
            float pa[4] = {pk.x, pk.y, pk.z, pk.w};
            float va[4] = {vv.x, vv.y, vv.z, vv.w};
            #pragma unroll
            for (int i = 0; i < 4; i++)
                #pragma unroll
                for (int j = 0; j < 4; j++) acc[i][j] += pa[i] * va[j];
            if (e0 == 0) {
                #pragma unroll
                for (int i = 0; i < 4; i++) ks[i] += pa[i];
            }
        }
        __syncthreads();
    }
    float* kvb = kv + (size_t)bh * 4096;
    #pragma unroll
    for (int i = 0; i < 4; i++)
        #pragma unroll
        for (int j = 0; j < 4; j++)
            atomicAdd(&kvb[(d0 + i) * 64 + e0 + j], acc[i][j]);
    if (e0 == 0) {
        #pragma unroll
        for (int i = 0; i < 4; i++) atomicAdd(&ksum[bh * 64 + d0 + i], ks[i]);
    }
}

__global__ void ksum_s0_kernel(const float* __restrict__ bkk, const float* __restrict__ s0,
                               float* __restrict__ ksum)
{
    int bh = blockIdx.x, h = bh & 7;
    int d = threadIdx.x;
    ksum[bh * 64 + d] += s0[bh] * (tanhf(bkk[h * 64 + d]) + 1.0f);
}

__global__ void attnout_kernel(const float* __restrict__ phiQ, const float* __restrict__ kv,
                               const float* __restrict__ bottom, float* __restrict__ out)
{
    int bh = blockIdx.y, b = bh >> 3, h = bh & 7;
    int ltile = blockIdx.x;
    __shared__ float kvs[4096];
    __shared__ float pqs[4][64];
    int tid = threadIdx.x;
    const float* kvb = kv + (size_t)bh * 4096;
    for (int i = tid; i < 4096; i += 256) kvs[i] = kvb[i];
    int rr = tid >> 6, e = tid & 63;
    size_t rowc = (size_t)b * NL + (size_t)ltile * 64;
    for (int r0 = 0; r0 < 64; r0 += 4) {
        __syncthreads();
        pqs[rr][e] = phiQ[(rowc + r0 + rr) * NC + h * 64 + e];
        __syncthreads();
        float num = 0.f;
        #pragma unroll
        for (int d = 0; d < 64; d++) num += pqs[rr][d] * kvs[d * 64 + e];
        int l = ltile * 64 + r0 + rr;
        float bot = bottom[(size_t)bh * NL + l] + 1e-6f;
        out[(rowc + r0 + rr) * NC + h * 64 + e] = num / bot;
    }
}

// ---------------------------------------------------------------------------
extern "C" void kernel_launch(void* const* d_in, const int* in_sizes, int n_in,
                              void* d_out, int out_size)
{
    (void)in_sizes; (void)n_in; (void)out_size;
    const float* x      = (const float*)d_in[0];
    const float* Wq     = (const float*)d_in[1];
    const float* bq     = (const float*)d_in[2];
    const float* gq     = (const float*)d_in[3];
    const float* betaq  = (const float*)d_in[4];
    const float* Wk     = (const float*)d_in[5];
    const float* bk     = (const float*)d_in[6];
    const float* gk     = (const float*)d_in[7];
    const float* betak  = (const float*)d_in[8];
    const float* Wv     = (const float*)d_in[9];
    const float* bv     = (const float*)d_in[10];
    const float* gv     = (const float*)d_in[11];
    const float* betav  = (const float*)d_in[12];
    const float* Wkq    = (const float*)d_in[13];
    const float* bkq    = (const float*)d_in[14];
    const float* Wkk    = (const float*)d_in[15];
    const float* bkk    = (const float*)d_in[16];
    const float* gat    = (const float*)d_in[17];
    const float* bat    = (const float*)d_in[18];
    const float* W1     = (const float*)d_in[19];
    const float* b1     = (const float*)d_in[20];
    const float* W2     = (const float*)d_in[21];
    const float* b2     = (const float*)d_in[22];
    float* out = (float*)d_out;

    float *xf, *Q, *K, *V, *phiQ, *phiK, *attn, *aln, *res, *hid;
    float *probe, *score, *bot, *s0, *kv, *ksum;
    __half *WqT, *WkT, *WvT, *WkqT, *WkkT, *W1T, *W2T;
    cudaGetSymbolAddress((void**)&xf,    g_xf);
    cudaGetSymbolAddress((void**)&Q,     g_Q);
    cudaGetSymbolAddress((void**)&K,     g_K);
    cudaGetSymbolAddress((void**)&V,     g_V);
    cudaGetSymbolAddress((void**)&phiQ,  g_phiQ);
    cudaGetSymbolAddress((void**)&phiK,  g_phiK);
    cudaGetSymbolAddress((void**)&attn,  g_attn);
    cudaGetSymbolAddress((void**)&aln,   g_aln);
    cudaGetSymbolAddress((void**)&res,   g_res);
    cudaGetSymbolAddress((void**)&hid,   g_hid);
    cudaGetSymbolAddress((void**)&probe, g_probe);
    cudaGetSymbolAddress((void**)&score, g_score);
    cudaGetSymbolAddress((void**)&bot,   g_bot);
    cudaGetSymbolAddress((void**)&s0,    g_s0);
    cudaGetSymbolAddress((void**)&kv,    g_kv);
    cudaGetSymbolAddress((void**)&ksum,  g_ksum);
    cudaGetSymbolAddress((void**)&WqT,   g_WqT);
    cudaGetSymbolAddress((void**)&WkT,   g_WkT);
    cudaGetSymbolAddress((void**)&WvT,   g_WvT);
    cudaGetSymbolAddress((void**)&WkqT,  g_WkqT);
    cudaGetSymbolAddress((void**)&WkkT,  g_WkkT);
    cudaGetSymbolAddress((void**)&W1T,   g_W1T);
    cudaGetSymbolAddress((void**)&W2T,   g_W2T);

    cudaFuncSetAttribute(gemm_mma<0>, cudaFuncAttributeMaxDynamicSharedMemorySize, GSMEM);
    cudaFuncSetAttribute(gemm_mma<1>, cudaFuncAttributeMaxDynamicSharedMemorySize, GSMEM);
    cudaFuncSetAttribute(gemm_mma<2>, cudaFuncAttributeMaxDynamicSharedMemorySize, GSMEM);
    cudaFuncSetAttribute(gemm_mma<3>, cudaFuncAttributeMaxDynamicSharedMemorySize, GSMEM);

    dim3 tgrid(NL / 32, NC / 32, NB), tblk(32, 8);
    dim3 wt512(NC / 32, NC / 32);

    // Launch order arranged so ncu's (-s 5 -c 1) 6th launch is gemm_mma<0>.
    transpose_in_kernel<<<tgrid, tblk>>>(x, xf);                 // 1
    wtrans_kernel<<<wt512, tblk>>>(Wq,  WqT,  NC, NC);           // 2
    wtrans_kernel<<<wt512, tblk>>>(Wk,  WkT,  NC, NC);           // 3
    wtrans_kernel<<<wt512, tblk>>>(Wv,  WvT,  NC, NC);           // 4
    wtrans_kernel<<<wt512, tblk>>>(Wkq, WkqT, NC, NC);           // 5

    dim3 gC(NC / 128, NM / 128);                // (4, 128)
    gemm_mma<0><<<gC, 256, GSMEM>>>(xf, WqT, bq, Q, NM, NC, NC, nullptr);   // 6 (profiled)
    gemm_mma<0><<<gC, 256, GSMEM>>>(xf, WkT, bk, K, NM, NC, NC, nullptr);
    gemm_mma<0><<<gC, 256, GSMEM>>>(xf, WvT, bv, V, NM, NC, NC, nullptr);

    wtrans_kernel<<<wt512, tblk>>>(Wkk, WkkT, NC, NC);
    wtrans_kernel<<<dim3(NMLP / 32, NC / 32), tblk>>>(W1, W1T, NC, NMLP);
    wtrans_kernel<<<dim3(NC / 32, NMLP / 32), tblk>>>(W2, W2T, NMLP, NC);

    layernorm_kernel<<<NM, 128>>>(Q, Q, gq, betaq);
    layernorm_kernel<<<NM, 128>>>(K, K, gk, betak);
    layernorm_kernel<<<NM, 128>>>(V, V, gv, betav);

    zero_kernel<<<(NB * NC + 255) / 256, 256>>>(probe, NB * NC);
    zero_kernel<<<(NB * NH * NDH * NDH + 255) / 256, 256>>>(kv, NB * NH * NDH * NDH);
    zero_kernel<<<(NB * NH * NDH + 255) / 256, 256>>>(ksum, NB * NH * NDH);

    probe_kernel<<<dim3(NB, 32), 512>>>(Q, probe);

    gemm_mma<1><<<gC, 256, GSMEM>>>(Q, WkqT, bkq, phiQ, NM, NC, NC, nullptr);
    gemm_mma<1><<<gC, 256, GSMEM>>>(K, WkkT, bkk, phiK, NM, NC, NC, nullptr);

    headdot_kernel<<<(NB * NL) / 8, 256>>>(K, probe, score, 1.0f / ((float)NL * 8.0f));
    softmax_kernel<<<NB * NH, 256>>>(score, s0);

    kv_kernel<<<dim3(NB * NH, 8), 256>>>(phiK, V, score, kv, ksum);
    ksum_s0_kernel<<<NB * NH, 64>>>(bkk, s0, ksum);

    headdot_kernel<<<(NB * NL) / 8, 256>>>(phiQ, ksum, bot, 1.0f);
    attnout_kernel<<<dim3(NL / 64, NB * NH), 256>>>(phiQ, kv, bot, attn);

    layernorm_kernel<<<NM, 128>>>(attn, aln, gat, bat);

    dim3 gUp(NMLP / 128, NM / 128);             // (16, 128)
    gemm_mma<2><<<gUp, 256, GSMEM>>>(aln, W1T, b1, hid, NM, NMLP, NC, nullptr);
    gemm_mma<3><<<gC, 256, GSMEM>>>(hid, W2T, b2, res, NM, NC, NMLP, aln);

    final_kernel<<<tgrid, tblk>>>(res, x, out);
}

// round 5
// speedup vs baseline: 4.1880x; 1.2980x over previous
#include <cuda_runtime.h>
#include <cuda_fp16.h>
#include <cstdint>

// ---------------------------------------------------------------------------
// LinearSelfAttentionBlock  (B=4, C=512, L=4096, H=8, DH=64, MLP=2048)
// Round 5: fp16 mma m16n8k16, BK=32, 3-stage cp.async, 2 CTA/SM,
// fp16 xf/hid (cp.async A-operands), final transpose fused into MLP-down.
// ---------------------------------------------------------------------------

constexpr int NB   = 4;
constexpr int NC   = 512;
constexpr int NL   = 4096;
constexpr int NH   = 8;
constexpr int NDH  = 64;
constexpr int NMLP = 2048;
constexpr int NM   = NB * NL;          // 16384 rows

// ------------------------- scratch (device globals) ------------------------
__device__ __align__(16) __half g_xfh [NM * NC];
__device__ float g_Q    [NM * NC];
__device__ float g_K    [NM * NC];
__device__ float g_V    [NM * NC];
__device__ float g_phiQ [NM * NC];
__device__ float g_phiK [NM * NC];
__device__ float g_attn [NM * NC];
__device__ float g_aln  [NM * NC];
__device__ __align__(16) __half g_hidh[NM * NMLP];
__device__ float g_probe[NB * NC];
__device__ float g_score[NB * NH * NL];
__device__ float g_bot  [NB * NH * NL];
__device__ float g_s0   [NB * NH];
__device__ float g_kv   [NB * NH * NDH * NDH];
__device__ float g_ksum [NB * NH * NDH];
// fp16 transposed weights (Bt[n,k] = W[k,n])
__device__ __align__(16) __half g_WqT [NC * NC];
__device__ __align__(16) __half g_WkT [NC * NC];
__device__ __align__(16) __half g_WvT [NC * NC];
__device__ __align__(16) __half g_WkqT[NC * NC];
__device__ __align__(16) __half g_WkkT[NC * NC];
__device__ __align__(16) __half g_W1T [NC * NMLP];
__device__ __align__(16) __half g_W2T [NMLP * NC];

// ------------------------- helpers -----------------------------------------
__device__ __forceinline__ uint32_t smem_u32(const void* p) {
    uint32_t a;
    asm("{ .reg .u64 t; cvta.to.shared.u64 t, %1; cvt.u32.u64 %0, t; }" : "=r"(a) : "l"(p));
    return a;
}
__device__ __forceinline__ uint32_t f2h2(float a, float b) {
    __half2 h = __float22half2_rn(make_float2(a, b));
    return *reinterpret_cast<uint32_t*>(&h);
}

#define CP_ASYNC16(dst, src) \
    asm volatile("cp.async.cg.shared.global [%0], [%1], 16;" :: "r"(dst), "l"(src))
#define CP_COMMIT() asm volatile("cp.async.commit_group;" ::: "memory")
#define CP_WAIT0()  asm volatile("cp.async.wait_group 0;" ::: "memory")
#define CP_WAIT1()  asm volatile("cp.async.wait_group 1;" ::: "memory")

#define LDSM_X4(r0, r1, r2, r3, a)                                             \
    asm volatile("ldmatrix.sync.aligned.m8n8.x4.shared.b16 {%0,%1,%2,%3}, [%4];" \
                 : "=r"(r0), "=r"(r1), "=r"(r2), "=r"(r3) : "r"(a))
#define LDSM_X2(r0, r1, a)                                                     \
    asm volatile("ldmatrix.sync.aligned.m8n8.x2.shared.b16 {%0,%1}, [%2];"     \
                 : "=r"(r0), "=r"(r1) : "r"(a))

__device__ __forceinline__ void mma_f16(float& d0, float& d1, float& d2, float& d3,
                                        uint32_t a0, uint32_t a1, uint32_t a2, uint32_t a3,
                                        uint32_t b0, uint32_t b1)
{
    asm volatile(
        "mma.sync.aligned.m16n8k16.row.col.f32.f16.f16.f32 "
        "{%0,%1,%2,%3}, {%4,%5,%6,%7}, {%8,%9}, {%0,%1,%2,%3};"
        : "+f"(d0), "+f"(d1), "+f"(d2), "+f"(d3)
        : "r"(a0), "r"(a1), "r"(a2), "r"(a3), "r"(b0), "r"(b1));
}

// ------------------------- tensor-core GEMM  D = A[M,K] * Bt[N,K]^T --------
// Tile 128x128, BK=32, 256 threads (8 warps 2x4 -> 64x32 warp tiles),
// 3-stage cp.async pipeline, 2 CTA/SM. Rows in smem: 32 halves = 64B,
// 16B-group swizzle: g' = g ^ ((row>>1)&3).
// EPI: 0 = +bias ; 1 = tanh(+bias)+1 ; 2 = gelu(+bias) (half out) ;
//      3 = +bias+resid, then transposed write out[b,c,l] = v + x[b,c,l].
constexpr int STAGE   = 16384;         // A 8KB + B 8KB
constexpr int GSMEM   = 3 * STAGE;     // 48KB

template <int EPI, bool AH, bool OH>
__global__ void __launch_bounds__(256, 2)
gemm_mma(const void* __restrict__ Ap, const __half* __restrict__ Bt,
         const float* __restrict__ bias, void* __restrict__ Outp,
         int M, int N, int K, const float* __restrict__ resid,
         const float* __restrict__ xin)
{
    extern __shared__ char smem[];
    const uint32_t sbu = smem_u32(smem);
    const int tid  = threadIdx.x;
    const int lane = tid & 31, wid = tid >> 5;
    const int wrow = (wid >> 2) * 64;
    const int wcol = (wid & 3) * 32;
    const int br0 = blockIdx.y * 128, bc0 = blockIdx.x * 128;

    const float*  Af = AH ? nullptr : (const float*)Ap + (size_t)br0 * K;
    const __half* Ah = AH ? (const __half*)Ap + (size_t)br0 * K : nullptr;
    const __half* Bb = Bt + (size_t)bc0 * K;

    float acc[4][4][4];
    #pragma unroll
    for (int i = 0; i < 4; i++)
        #pragma unroll
        for (int j = 0; j < 4; j++)
            #pragma unroll
            for (int q = 0; q < 4; q++) acc[i][j][q] = 0.f;

    // staging: 512 16B-chunks per tile; thread handles idx = tid, tid+256
    int srow[2], sg[2];
    uint32_t ssw[2];
    #pragma unroll
    for (int i = 0; i < 2; i++) {
        int idx = tid + i * 256;
        srow[i] = idx >> 2;
        sg[i]   = idx & 3;
        ssw[i]  = (uint32_t)srow[i] * 64u +
                  ((uint32_t)(sg[i] ^ ((srow[i] >> 1) & 3)) << 4);
    }

    const int nk = K >> 5;

    // prologue: issue stages 0,1 for B (and A if AH); load A(0) regs if !AH
    #pragma unroll
    for (int st = 0; st < 2; st++) {
        const int k0 = st << 5;
        const uint32_t so = sbu + (uint32_t)st * STAGE;
        #pragma unroll
        for (int i = 0; i < 2; i++) {
            if (AH) CP_ASYNC16(so + ssw[i], Ah + (size_t)srow[i] * K + k0 + sg[i] * 8);
            CP_ASYNC16(so + 8192u + ssw[i], Bb + (size_t)srow[i] * K + k0 + sg[i] * 8);
        }
        CP_COMMIT();
    }

    uint4 pa[2];
    if (!AH) {
        #pragma unroll
        for (int i = 0; i < 2; i++) {
            const float4* p = reinterpret_cast<const float4*>(Af + (size_t)srow[i] * K + sg[i] * 8);
            float4 f0 = p[0], f1 = p[1];
            pa[i] = make_uint4(f2h2(f0.x, f0.y), f2h2(f0.z, f0.w),
                               f2h2(f1.x, f1.y), f2h2(f1.z, f1.w));
        }
    }

    for (int ch = 0; ch < nk; ch++) {
        const uint32_t so = sbu + (uint32_t)(ch % 3) * STAGE;
        if (ch + 1 < nk) CP_WAIT1(); else CP_WAIT0();
        if (!AH) {
            #pragma unroll
            for (int i = 0; i < 2; i++)
                *reinterpret_cast<uint4*>(smem + (ch % 3) * STAGE + ssw[i]) = pa[i];
        }
        __syncthreads();

        if (ch + 2 < nk) {
            const int k0 = (ch + 2) << 5;
            const uint32_t sn = sbu + (uint32_t)((ch + 2) % 3) * STAGE;
            #pragma unroll
            for (int i = 0; i < 2; i++) {
                if (AH) CP_ASYNC16(sn + ssw[i], Ah + (size_t)srow[i] * K + k0 + sg[i] * 8);
                CP_ASYNC16(sn + 8192u + ssw[i], Bb + (size_t)srow[i] * K + k0 + sg[i] * 8);
            }
            CP_COMMIT();
        }
        if (!AH && ch + 1 < nk) {
            const int k0 = (ch + 1) << 5;
            #pragma unroll
            for (int i = 0; i < 2; i++) {
                const float4* p = reinterpret_cast<const float4*>(
                    Af + (size_t)srow[i] * K + k0 + sg[i] * 8);
                float4 f0 = p[0], f1 = p[1];
                pa[i] = make_uint4(f2h2(f0.x, f0.y), f2h2(f0.z, f0.w),
                                   f2h2(f1.x, f1.y), f2h2(f1.z, f1.w));
            }
        }

        // compute 2 k16 steps
        const uint32_t sAu = so, sBu = so + 8192u;
        #pragma unroll
        for (int ks = 0; ks < 2; ks++) {
            uint32_t afr[4][4], bfr[4][2];
            #pragma unroll
            for (int mt = 0; mt < 4; mt++) {
                int row = wrow + mt * 16 + (lane & 15);
                uint32_t g = 2u * ks + (uint32_t)(lane >> 4);
                uint32_t ad = sAu + (uint32_t)row * 64u +
                              ((g ^ (uint32_t)((row >> 1) & 3)) << 4);
                LDSM_X4(afr[mt][0], afr[mt][1], afr[mt][2], afr[mt][3], ad);
            }
            #pragma unroll
            for (int nt = 0; nt < 4; nt++) {
                int row = wcol + nt * 8 + (lane & 7);
                uint32_t g = 2u * ks + (uint32_t)((lane >> 3) & 1);
                uint32_t bd = sBu + (uint32_t)row * 64u +
                              ((g ^ (uint32_t)((row >> 1) & 3)) << 4);
                LDSM_X2(bfr[nt][0], bfr[nt][1], bd);
            }
            #pragma unroll
            for (int mt = 0; mt < 4; mt++)
                #pragma unroll
                for (int nt = 0; nt < 4; nt++)
                    mma_f16(acc[mt][nt][0], acc[mt][nt][1], acc[mt][nt][2], acc[mt][nt][3],
                            afr[mt][0], afr[mt][1], afr[mt][2], afr[mt][3],
                            bfr[nt][0], bfr[nt][1]);
        }
        __syncthreads();
    }

    // ------------------------- epilogue -------------------------
    const int r = lane >> 2, c = lane & 3;

    if (EPI == 3) {
        // transposed write: out[b, col, l] = acc + bias + resid + x[b, col, l]
        float* ts = reinterpret_cast<float*>(smem);   // [64][132]
        const int b  = br0 / NL;
        const int l0 = br0 % NL;
        float* Out = (float*)Outp;
        #pragma unroll
        for (int h = 0; h < 2; h++) {
            if ((wid >> 2) == h) {
                #pragma unroll
                for (int mt = 0; mt < 4; mt++) {
                    #pragma unroll
                    for (int h8 = 0; h8 < 2; h8++) {
                        int rrl = mt * 16 + h8 * 8 + r;
                        int grow = br0 + h * 64 + rrl;
                        size_t ro = (size_t)grow * N;
                        #pragma unroll
                        for (int nt = 0; nt < 4; nt++) {
                            int cl = wcol + nt * 8 + c * 2;
                            int coln = bc0 + cl;
                            ts[rrl * 132 + cl]     = acc[mt][nt][h8 * 2 + 0] + bias[coln]     + resid[ro + coln];
                            ts[rrl * 132 + cl + 1] = acc[mt][nt][h8 * 2 + 1] + bias[coln + 1] + resid[ro + coln + 1];
                        }
                    }
                }
            }
            __syncthreads();
            #pragma unroll
            for (int i = 0; i < 8; i++) {
                int idx = tid + i * 256;
                int cc = idx >> 4, lq = idx & 15;
                size_t go = ((size_t)b * NC + bc0 + cc) * NL + l0 + h * 64 + lq * 4;
                float4 xv = *reinterpret_cast<const float4*>(xin + go);
                float4 o;
                o.x = ts[(lq * 4 + 0) * 132 + cc] + xv.x;
                o.y = ts[(lq * 4 + 1) * 132 + cc] + xv.y;
                o.z = ts[(lq * 4 + 2) * 132 + cc] + xv.z;
                o.w = ts[(lq * 4 + 3) * 132 + cc] + xv.w;
                *reinterpret_cast<float4*>(Out + go) = o;
            }
            __syncthreads();
        }
        return;
    }

    #pragma unroll
    for (int mt = 0; mt < 4; mt++) {
        int row0 = br0 + wrow + mt * 16 + r;
        #pragma unroll
        for (int half = 0; half < 2; half++) {
            int row = row0 + half * 8;
            size_t ro = (size_t)row * N;
            #pragma unroll
            for (int nt = 0; nt < 4; nt++) {
                int col = bc0 + wcol + nt * 8 + c * 2;
                float v0 = acc[mt][nt][half * 2 + 0] + bias[col];
                float v1 = acc[mt][nt][half * 2 + 1] + bias[col + 1];
                if (EPI == 1) {
                    v0 = tanhf(v0) + 1.0f;
                    v1 = tanhf(v1) + 1.0f;
                } else if (EPI == 2) {
                    v0 = 0.5f * v0 * (1.0f + erff(v0 * 0.70710678118654752f));
                    v1 = 0.5f * v1 * (1.0f + erff(v1 * 0.70710678118654752f));
                }
                if (OH) {
                    __half2 hv = __floats2half2_rn(v0, v1);
                    *reinterpret_cast<__half2*>((__half*)Outp + ro + col) = hv;
                } else {
                    float2 o = {v0, v1};
                    *reinterpret_cast<float2*>((float*)Outp + ro + col) = o;
                }
            }
        }
    }
}

// ------------------- weight transpose + fp16: Wt[n,k] = W[k,n] -------------
__global__ void wtrans_kernel(const float* __restrict__ W, __half* __restrict__ Wt,
                              int R, int Cc)
{
    __shared__ float t[32][33];
    int r0 = blockIdx.y * 32, c0 = blockIdx.x * 32;
    #pragma unroll
    for (int i = threadIdx.y; i < 32; i += 8)
        t[i][threadIdx.x] = W[(size_t)(r0 + i) * Cc + c0 + threadIdx.x];
    __syncthreads();
    #pragma unroll
    for (int i = threadIdx.y; i < 32; i += 8)
        Wt[(size_t)(c0 + i) * R + r0 + threadIdx.x] = __float2half_rn(t[threadIdx.x][i]);
}

// --------------- transpose x[B,C,L] -> xfh[B,L,C] (fp16) -------------------
__global__ void transpose_in_kernel(const float* __restrict__ x, __half* __restrict__ xf)
{
    __shared__ float tile[32][33];
    int b  = blockIdx.z;
    int l0 = blockIdx.x * 32, c0 = blockIdx.y * 32;
    const float* xb = x + (size_t)b * NC * NL;
    #pragma unroll
    for (int i = threadIdx.y; i < 32; i += 8)
        tile[i][threadIdx.x] = xb[(size_t)(c0 + i) * NL + l0 + threadIdx.x];
    __syncthreads();
    __half* xfb = xf + (size_t)b * NL * NC;
    #pragma unroll
    for (int i = threadIdx.y; i < 32; i += 8)
        xfb[(size_t)(l0 + i) * NC + c0 + threadIdx.x] = __float2half_rn(tile[threadIdx.x][i]);
}

// ------------------------- layernorm over rows of 512 ----------------------
__global__ void layernorm_kernel(const float* __restrict__ in, float* __restrict__ out,
                                 const float* __restrict__ gamma, const float* __restrict__ beta)
{
    int row = blockIdx.x;
    int tid = threadIdx.x;                      // 128 threads, 4 floats each
    const float4 v = reinterpret_cast<const float4*>(in + (size_t)row * NC)[tid];
    __shared__ float sh[4];

    float s = v.x + v.y + v.z + v.w;
    #pragma unroll
    for (int o = 16; o > 0; o >>= 1) s += __shfl_xor_sync(0xffffffffu, s, o);
    if ((tid & 31) == 0) sh[tid >> 5] = s;
    __syncthreads();
    float mean = (sh[0] + sh[1] + sh[2] + sh[3]) * (1.0f / NC);
    __syncthreads();

    float dx = v.x - mean, dy = v.y - mean, dz = v.z - mean, dw = v.w - mean;
    float q = dx * dx + dy * dy + dz * dz + dw * dw;
    #pragma unroll
    for (int o = 16; o > 0; o >>= 1) q += __shfl_xor_sync(0xffffffffu, q, o);
    if ((tid & 31) == 0) sh[tid >> 5] = q;
    __syncthreads();
    float var = (sh[0] + sh[1] + sh[2] + sh[3]) * (1.0f / NC);
    float inv = rsqrtf(var + 1e-5f);

    float4 g  = reinterpret_cast<const float4*>(gamma)[tid];
    float4 bb = reinterpret_cast<const float4*>(beta)[tid];
    float4 o4;
    o4.x = dx * inv * g.x + bb.x;
    o4.y = dy * inv * g.y + bb.y;
    o4.z = dz * inv * g.z + bb.z;
    o4.w = dw * inv * g.w + bb.w;
    reinterpret_cast<float4*>(out + (size_t)row * NC)[tid] = o4;
}

// ------------------------- misc small kernels ------------------------------
__global__ void zero_kernel(float* __restrict__ p, int n)
{
    int i = blockIdx.x * blockDim.x + threadIdx.x;
    if (i < n) p[i] = 0.f;
}

__global__ void probe_kernel(const float* __restrict__ Q, float* __restrict__ probe)
{
    int b = blockIdx.x, chunk = blockIdx.y;
    int c = threadIdx.x;                        // 512 threads
    float s = 0.f;
    size_t base = ((size_t)b * NL + (size_t)chunk * 128) * NC + c;
    for (int i = 0; i < 128; i++) s += Q[base + (size_t)i * NC];
    atomicAdd(&probe[b * NC + c], s);
}

__global__ void headdot_kernel(const float* __restrict__ rows, const float* __restrict__ vecs,
                               float* __restrict__ out, float scale)
{
    int warp = (blockIdx.x * blockDim.x + threadIdx.x) >> 5;
    int lane = threadIdx.x & 31;
    if (warp >= NB * NL) return;
    int b = warp / NL, l = warp % NL;
    const float* row = rows + (size_t)warp * NC;
    const float* vec = vecs + (size_t)b * NC;
    float p[8];
    #pragma unroll
    for (int h = 0; h < 8; h++) p[h] = 0.f;
    #pragma unroll
    for (int j = 0; j < 16; j++) {
        int c = lane + 32 * j;
        p[j >> 1] += row[c] * vec[c];
    }
    #pragma unroll
    for (int h = 0; h < 8; h++) {
        float v = p[h];
        #pragma unroll
        for (int o = 16; o > 0; o >>= 1) v += __shfl_xor_sync(0xffffffffu, v, o);
        p[h] = v;
    }
    if (lane == 0) {
        #pragma unroll
        for (int h = 0; h < 8; h++)
            out[((size_t)b * NH + h) * NL + l] = p[h] * scale;
    }
}

__global__ void softmax_kernel(float* __restrict__ score, float* __restrict__ s0)
{
    int bh = blockIdx.x;
    float* s = score + (size_t)bh * NL;
    int tid = threadIdx.x;                      // 256 threads
    __shared__ float sh[8];
    __shared__ float bc2[2];

    float m = 0.0f;                             // includes zero-token score 0
    for (int i = tid; i < NL; i += 256) m = fmaxf(m, s[i]);
    #pragma unroll
    for (int o = 16; o > 0; o >>= 1) m = fmaxf(m, __shfl_xor_sync(0xffffffffu, m, o));
    if ((tid & 31) == 0) sh[tid >> 5] = m;
    __syncthreads();
    if (tid == 0) {
        float mm = sh[0];
        for (int i = 1; i < 8; i++) mm = fmaxf(mm, sh[i]);
        bc2[0] = mm;
    }
    __syncthreads();
    m = bc2[0];

    float sum = 0.f;
    for (int i = tid; i < NL; i += 256) sum += expf(s[i] - m);
    #pragma unroll
    for (int o = 16; o > 0; o >>= 1) sum += __shfl_xor_sync(0xffffffffu, sum, o);
    if ((tid & 31) == 0) sh[tid >> 5] = sum;
    __syncthreads();
    if (tid == 0) {
        float t = expf(-m);                     // zero token
        for (int i = 0; i < 8; i++) t += sh[i];
        bc2[1] = 1.0f / t;
    }
    __syncthreads();
    float inv = bc2[1];
    for (int i = tid; i < NL; i += 256) s[i] = expf(s[i] - m) * inv;
    if (tid == 0) s0[bh] = expf(-m) * inv;
}

__global__ void kv_kernel(const float* __restrict__ phiK, const float* __restrict__ V,
                          const float* __restrict__ score, float* __restrict__ kv,
                          float* __restrict__ ksum)
{
    int bh = blockIdx.x, b = bh >> 3, h = bh & 7;
    int l0 = blockIdx.y * (NL / 8);             // 512-row chunk
    __shared__ float pks[8][64];
    __shared__ float vs[8][64];
    int tid = threadIdx.x;
    int d0 = (tid >> 4) << 2;
    int e0 = (tid & 15) << 2;
    float acc[4][4];
    #pragma unroll
    for (int i = 0; i < 4; i++)
        #pragma unroll
        for (int j = 0; j < 4; j++) acc[i][j] = 0.f;
    float ks[4] = {0.f, 0.f, 0.f, 0.f};

    const size_t base = ((size_t)b * NL) * NC + (size_t)h * 64;
    const float* scb = score + (size_t)bh * NL;

    for (int lt = 0; lt < NL / 8; lt += 8) {
        #pragma unroll
        for (int s = 0; s < 2; s++) {
            int idx = tid + (s << 8);
            int r = idx >> 6, col = idx & 63;
            int l = l0 + lt + r;
            size_t off = base + (size_t)l * NC + col;
            pks[r][col] = phiK[off] * scb[l];
            vs[r][col]  = V[off];
        }
        __syncthreads();
        #pragma unroll
        for (int r = 0; r < 8; r++) {
            float4 pk = *reinterpret_cast<const float4*>(&pks[r][d0]);
            float4 vv = *reinterpret_cast<const float4*>(&vs[r][e0]);
            float pa[4] = {pk.x, pk.y, pk.z, pk.w};
            float va[4] = {vv.x, vv.y, vv.z, vv.w};
            #pragma unroll
            for (int i = 0; i < 4; i++)
                #pragma unroll
                for (int j = 0; j < 4; j++) acc[i][j] += pa[i] * va[j];
            if (e0 == 0) {
                #pragma unroll
                for (int i = 0; i < 4; i++) ks[i] += pa[i];
            }
        }
        __syncthreads();
    }
    float* kvb = kv + (size_t)bh * 4096;
    #pragma unroll
    for (int i = 0; i < 4; i++)
        #pragma unroll
        for (int j = 0; j < 4; j++)
            atomicAdd(&kvb[(d0 + i) * 64 + e0 + j], acc[i][j]);
    if (e0 == 0) {
        #pragma unroll
        for (int i = 0; i < 4; i++) atomicAdd(&ksum[bh * 64 + d0 + i], ks[i]);
    }
}

__global__ void ksum_s0_kernel(const float* __restrict__ bkk, const float* __restrict__ s0,
                               float* __restrict__ ksum)
{
    int bh = blockIdx.x, h = bh & 7;
    int d = threadIdx.x;
    ksum[bh * 64 + d] += s0[bh] * (tanhf(bkk[h * 64 + d]) + 1.0f);
}

__global__ void attnout_kernel(const float* __restrict__ phiQ, const float* __restrict__ kv,
                               const float* __restrict__ bottom, float* __restrict__ out)
{
    int bh = blockIdx.y, b = bh >> 3, h = bh & 7;
    int ltile = blockIdx.x;
    __shared__ float kvs[4096];
    __shared__ float pqs[4][64];
    int tid = threadIdx.x;
    const float* kvb = kv + (size_t)bh * 4096;
    for (int i = tid; i < 4096; i += 256) kvs[i] = kvb[i];
    int rr = tid >> 6, e = tid & 63;
    size_t rowc = (size_t)b * NL + (size_t)ltile * 64;
    for (int r0 = 0; r0 < 64; r0 += 4) {
        __syncthreads();
        pqs[rr][e] = phiQ[(rowc + r0 + rr) * NC + h * 64 + e];
        __syncthreads();
        float num = 0.f;
        #pragma unroll
        for (int d = 0; d < 64; d++) num += pqs[rr][d] * kvs[d * 64 + e];
        int l = ltile * 64 + r0 + rr;
        float bot = bottom[(size_t)bh * NL + l] + 1e-6f;
        out[(rowc + r0 + rr) * NC + h * 64 + e] = num / bot;
    }
}

// ---------------------------------------------------------------------------
extern "C" void kernel_launch(void* const* d_in, const int* in_sizes, int n_in,
                              void* d_out, int out_size)
{
    (void)in_sizes; (void)n_in; (void)out_size;
    const float* x      = (const float*)d_in[0];
    const float* Wq     = (const float*)d_in[1];
    const float* bq     = (const float*)d_in[2];
    const float* gq     = (const float*)d_in[3];
    const float* betaq  = (const float*)d_in[4];
    const float* Wk     = (const float*)d_in[5];
    const float* bk     = (const float*)d_in[6];
    const float* gk     = (const float*)d_in[7];
    const float* betak  = (const float*)d_in[8];
    const float* Wv     = (const float*)d_in[9];
    const float* bv     = (const float*)d_in[10];
    const float* gv     = (const float*)d_in[11];
    const float* betav  = (const float*)d_in[12];
    const float* Wkq    = (const float*)d_in[13];
    const float* bkq    = (const float*)d_in[14];
    const float* Wkk    = (const float*)d_in[15];
    const float* bkk    = (const float*)d_in[16];
    const float* gat    = (const float*)d_in[17];
    const float* bat    = (const float*)d_in[18];
    const float* W1     = (const float*)d_in[19];
    const float* b1     = (const float*)d_in[20];
    const float* W2     = (const float*)d_in[21];
    const float* b2     = (const float*)d_in[22];
    float* out = (float*)d_out;

    float *Q, *K, *V, *phiQ, *phiK, *attn, *aln;
    float *probe, *score, *bot, *s0, *kv, *ksum;
    __half *xfh, *hidh, *WqT, *WkT, *WvT, *WkqT, *WkkT, *W1T, *W2T;
    cudaGetSymbolAddress((void**)&xfh,   g_xfh);
    cudaGetSymbolAddress((void**)&Q,     g_Q);
    cudaGetSymbolAddress((void**)&K,     g_K);
    cudaGetSymbolAddress((void**)&V,     g_V);
    cudaGetSymbolAddress((void**)&phiQ,  g_phiQ);
    cudaGetSymbolAddress((void**)&phiK,  g_phiK);
    cudaGetSymbolAddress((void**)&attn,  g_attn);
    cudaGetSymbolAddress((void**)&aln,   g_aln);
    cudaGetSymbolAddress((void**)&hidh,  g_hidh);
    cudaGetSymbolAddress((void**)&probe, g_probe);
    cudaGetSymbolAddress((void**)&score, g_score);
    cudaGetSymbolAddress((void**)&bot,   g_bot);
    cudaGetSymbolAddress((void**)&s0,    g_s0);
    cudaGetSymbolAddress((void**)&kv,    g_kv);
    cudaGetSymbolAddress((void**)&ksum,  g_ksum);
    cudaGetSymbolAddress((void**)&WqT,   g_WqT);
    cudaGetSymbolAddress((void**)&WkT,   g_WkT);
    cudaGetSymbolAddress((void**)&WvT,   g_WvT);
    cudaGetSymbolAddress((void**)&WkqT,  g_WkqT);
    cudaGetSymbolAddress((void**)&WkkT,  g_WkkT);
    cudaGetSymbolAddress((void**)&W1T,   g_W1T);
    cudaGetSymbolAddress((void**)&W2T,   g_W2T);

    cudaFuncSetAttribute(gemm_mma<0, true,  false>, cudaFuncAttributeMaxDynamicSharedMemorySize, GSMEM);
    cudaFuncSetAttribute(gemm_mma<1, false, false>, cudaFuncAttributeMaxDynamicSharedMemorySize, GSMEM);
    cudaFuncSetAttribute(gemm_mma<2, false, true >, cudaFuncAttributeMaxDynamicSharedMemorySize, GSMEM);
    cudaFuncSetAttribute(gemm_mma<3, true,  false>, cudaFuncAttributeMaxDynamicSharedMemorySize, GSMEM);

    dim3 tgrid(NL / 32, NC / 32, NB), tblk(32, 8);
    dim3 wt512(NC / 32, NC / 32);
    dim3 gC(NC / 128, NM / 128);                // (4, 128)
    dim3 gUp(NMLP / 128, NM / 128);             // (16, 128)

    // Launch order: ncu (-s 5 -c 1) + 1 harness-poison launch => my launch #5
    // is profiled. Put the first GEMM there.
    transpose_in_kernel<<<tgrid, tblk>>>(x, xfh);                 // 1
    wtrans_kernel<<<wt512, tblk>>>(Wq,  WqT,  NC, NC);            // 2
    wtrans_kernel<<<wt512, tblk>>>(Wk,  WkT,  NC, NC);            // 3
    wtrans_kernel<<<wt512, tblk>>>(Wv,  WvT,  NC, NC);            // 4
    gemm_mma<0, true, false><<<gC, 256, GSMEM>>>(xfh, WqT, bq, Q, NM, NC, NC, nullptr, nullptr);  // 5 (profiled)
    gemm_mma<0, true, false><<<gC, 256, GSMEM>>>(xfh, WkT, bk, K, NM, NC, NC, nullptr, nullptr);
    gemm_mma<0, true, false><<<gC, 256, GSMEM>>>(xfh, WvT, bv, V, NM, NC, NC, nullptr, nullptr);

    wtrans_kernel<<<wt512, tblk>>>(Wkq, WkqT, NC, NC);
    wtrans_kernel<<<wt512, tblk>>>(Wkk, WkkT, NC, NC);
    wtrans_kernel<<<dim3(NMLP / 32, NC / 32), tblk>>>(W1, W1T, NC, NMLP);
    wtrans_kernel<<<dim3(NC / 32, NMLP / 32), tblk>>>(W2, W2T, NMLP, NC);

    layernorm_kernel<<<NM, 128>>>(Q, Q, gq, betaq);
    layernorm_kernel<<<NM, 128>>>(K, K, gk, betak);
    layernorm_kernel<<<NM, 128>>>(V, V, gv, betav);

    zero_kernel<<<(NB * NC + 255) / 256, 256>>>(probe, NB * NC);
    zero_kernel<<<(NB * NH * NDH * NDH + 255) / 256, 256>>>(kv, NB * NH * NDH * NDH);
    zero_kernel<<<(NB * NH * NDH + 255) / 256, 256>>>(ksum, NB * NH * NDH);

    probe_kernel<<<dim3(NB, 32), 512>>>(Q, probe);

    gemm_mma<1, false, false><<<gC, 256, GSMEM>>>(Q, WkqT, bkq, phiQ, NM, NC, NC, nullptr, nullptr);
    gemm_mma<1, false, false><<<gC, 256, GSMEM>>>(K, WkkT, bkk, phiK, NM, NC, NC, nullptr, nullptr);

    headdot_kernel<<<(NB * NL) / 8, 256>>>(K, probe, score, 1.0f / ((float)NL * 8.0f));
    softmax_kernel<<<NB * NH, 256>>>(score, s0);

    kv_kernel<<<dim3(NB * NH, 8), 256>>>(phiK, V, score, kv, ksum);
    ksum_s0_kernel<<<NB * NH, 64>>>(bkk, s0, ksum);

    headdot_kernel<<<(NB * NL) / 8, 256>>>(phiQ, ksum, bot, 1.0f);
    attnout_kernel<<<dim3(NL / 64, NB * NH), 256>>>(phiQ, kv, bot, attn);

    layernorm_kernel<<<NM, 128>>>(attn, aln, gat, bat);

    gemm_mma<2, false, true ><<<gUp, 256, GSMEM>>>(aln, W1T, b1, hidh, NM, NMLP, NC, nullptr, nullptr);
    gemm_mma<3, true,  false><<<gC, 256, GSMEM>>>(hidh, W2T, b2, out, NM, NC, NMLP, aln, x);
}